// round 2
// baseline (speedup 1.0000x reference)
#include <cuda_runtime.h>
#include <math.h>
#include <stdint.h>

// ---------------------------------------------------------------------------
// Problem constants (from setup_inputs): N=100000 nodes, F=256, E=1600000.
// Layer 1: 256 -> 8 heads x 16   (HC=128)
// Layer 2: 128 -> 8 heads x 8    (HC=64)
// Layer 3:  64 -> 1 head  x 10   (HC=10), then log_softmax
// ---------------------------------------------------------------------------
#define MAXN 100000
#define MAXE 1600000

// Scratch (device globals; allocation in kernel_launch is forbidden)
__device__ __align__(16) float g_xp[MAXN * 128];   // transformed features
__device__ __align__(16) float g_h [MAXN * 128];   // layer activations
__device__ float g_asrc[MAXN * 8];
__device__ float g_adst[MAXN * 8];
__device__ int   g_srcbuf[MAXE];
__device__ int   g_dstbuf[MAXE];
__device__ int   g_deg[MAXN];
__device__ int   g_cursor[MAXN];
__device__ int   g_row[MAXN + 1];
__device__ int   g_csr[MAXE + MAXN];   // src list, grouped by dst (self loop first)
__device__ int   g_is64;

// ---------------------------------------------------------------------------
// Edge dtype detection + conversion (edge_index may be int32 or int64)
// ---------------------------------------------------------------------------
__global__ void detect_kernel(const void* ei, int N) {
    // Interpret first 8 slots as int64. Random int32 pairs read as int64 are
    // >= 2^32 (unless the high word is 0 AND low word < N, astronomically
    // unlikely for 8 consecutive random ids), so this is a reliable test.
    const long long* p = (const long long*)ei;
    int ok = 1;
    for (int i = 0; i < 8; i++) {
        long long v = p[i];
        if (v < 0 || v >= (long long)N) ok = 0;
    }
    g_is64 = ok;
}

__global__ void convert_kernel(const void* ei, int E) {
    int e = blockIdx.x * blockDim.x + threadIdx.x;
    if (e >= E) return;
    if (g_is64) {
        const long long* p = (const long long*)ei;
        g_srcbuf[e] = (int)p[e];
        g_dstbuf[e] = (int)p[(size_t)E + e];
    } else {
        const int* p = (const int*)ei;
        g_srcbuf[e] = p[e];
        g_dstbuf[e] = p[(size_t)E + e];
    }
}

// ---------------------------------------------------------------------------
// CSR build
// ---------------------------------------------------------------------------
__global__ void init_deg_kernel(int N) {
    int i = blockIdx.x * blockDim.x + threadIdx.x;
    if (i < N) g_deg[i] = 1;  // implicit self loop
}

__global__ void hist_kernel(int E) {
    int e = blockIdx.x * blockDim.x + threadIdx.x;
    if (e < E) atomicAdd(&g_deg[g_dstbuf[e]], 1);
}

// Single-block exclusive scan over deg; also seeds self loops + cursors.
__global__ void scan_kernel(int N) {
    __shared__ int sums[1024];
    int t = threadIdx.x;
    int chunk = (N + 1023) / 1024;
    int lo = t * chunk;
    int hi = min(lo + chunk, N);
    int s = 0;
    for (int i = lo; i < hi; i++) s += g_deg[i];
    sums[t] = s;
    __syncthreads();
    for (int off = 1; off < 1024; off <<= 1) {
        int v = (t >= off) ? sums[t - off] : 0;
        __syncthreads();
        sums[t] += v;
        __syncthreads();
    }
    int run = (t == 0) ? 0 : sums[t - 1];
    for (int i = lo; i < hi; i++) {
        g_row[i] = run;
        g_csr[run] = i;          // self loop occupies first slot
        g_cursor[i] = run + 1;
        run += g_deg[i];
    }
    if (t == 1023) g_row[N] = sums[1023];
}

__global__ void scatter_kernel(int E) {
    int e = blockIdx.x * blockDim.x + threadIdx.x;
    if (e < E) {
        int dst = g_dstbuf[e];
        int src = g_srcbuf[e];
        int pos = atomicAdd(&g_cursor[dst], 1);
        g_csr[pos] = src;
    }
}

// ---------------------------------------------------------------------------
// GEMM: g_xp[N,KOUT] = A[N,KIN] @ W[KIN,KOUT]
// Block tile: BM rows x KOUT cols, K chunked by BK. Thread micro-tile TM x TN.
// ---------------------------------------------------------------------------
template <int KIN, int KOUT, int BM, int BK, int TM, int TN>
__global__ void gemm_kernel(const float* __restrict__ Ain, const float* __restrict__ W,
                            int N, int ostride) {
    const float* A = Ain ? Ain : g_h;   // layer>=2 reads g_h
    __shared__ float As[BM][BK];
    __shared__ float Bs[BK][KOUT];
    constexpr int TX = KOUT / TN;                 // threads along cols
    constexpr int NT = (BM / TM) * (KOUT / TN);   // total threads
    int tid = threadIdx.x;
    int tx = tid % TX, ty = tid / TX;
    int row0 = blockIdx.x * BM;

    float acc[TM][TN];
#pragma unroll
    for (int i = 0; i < TM; i++)
#pragma unroll
        for (int j = 0; j < TN; j++) acc[i][j] = 0.f;

    for (int k0 = 0; k0 < KIN; k0 += BK) {
#pragma unroll
        for (int i = tid; i < BM * BK; i += NT) {
            int m = i / BK, k = i % BK;
            int gr = row0 + m;
            As[m][k] = (gr < N) ? A[(size_t)gr * KIN + k0 + k] : 0.f;
        }
#pragma unroll
        for (int i = tid; i < BK * KOUT; i += NT) {
            int k = i / KOUT, n = i % KOUT;
            Bs[k][n] = W[(size_t)(k0 + k) * KOUT + n];
        }
        __syncthreads();
#pragma unroll
        for (int kk = 0; kk < BK; kk++) {
            float a[TM], b[TN];
#pragma unroll
            for (int i = 0; i < TM; i++) a[i] = As[ty * TM + i][kk];
#pragma unroll
            for (int j = 0; j < TN; j++) b[j] = Bs[kk][tx * TN + j];
#pragma unroll
            for (int i = 0; i < TM; i++)
#pragma unroll
                for (int j = 0; j < TN; j++) acc[i][j] += a[i] * b[j];
        }
        __syncthreads();
    }
#pragma unroll
    for (int i = 0; i < TM; i++) {
        int gr = row0 + ty * TM + i;
        if (gr < N) {
#pragma unroll
            for (int j = 0; j < TN; j++)
                g_xp[(size_t)gr * ostride + tx * TN + j] = acc[i][j];
        }
    }
}

// ---------------------------------------------------------------------------
// Per-node attention logits: asrc[n,h] = sum_c xp[n,h,c]*a_s[h,c]; same adst.
// One warp per node. VPL = H*C/32 values per lane, LPH lanes per head.
// ---------------------------------------------------------------------------
template <int H, int C>
__global__ void attn_kernel(const float* __restrict__ a_s, const float* __restrict__ a_d, int N) {
    constexpr int HC = H * C;
    constexpr int VPL = HC / 32;
    constexpr int LPH = C / VPL;
    int w = (blockIdx.x * blockDim.x + threadIdx.x) >> 5;
    int lane = threadIdx.x & 31;
    if (w >= N) return;
    int head = lane / LPH;
    const float* row = g_xp + (size_t)w * HC + lane * VPL;
    float ss = 0.f, sd = 0.f;
#pragma unroll
    for (int v = 0; v < VPL; v++) {
        float xv = row[v];
        ss += xv * a_s[lane * VPL + v];
        sd += xv * a_d[lane * VPL + v];
    }
#pragma unroll
    for (int off = LPH / 2; off >= 1; off >>= 1) {
        ss += __shfl_xor_sync(0xFFFFFFFFu, ss, off);
        sd += __shfl_xor_sync(0xFFFFFFFFu, sd, off);
    }
    if ((lane % LPH) == 0) {
        g_asrc[(size_t)w * H + head] = ss;
        g_adst[(size_t)w * H + head] = sd;
    }
}

// ---------------------------------------------------------------------------
// Aggregation: per destination node (warp-per-dst), online softmax over CSR
// neighbor list (self loop included), output = sum alpha*xp[src] + bias, ELU.
// ---------------------------------------------------------------------------
template <int H, int C, bool DO_ELU>
__global__ void aggregate_kernel(const float* __restrict__ bias, int N) {
    constexpr int HC = H * C;
    constexpr int VPL = HC / 32;
    constexpr int LPH = C / VPL;
    int d = (blockIdx.x * blockDim.x + threadIdx.x) >> 5;
    int lane = threadIdx.x & 31;
    if (d >= N) return;
    int head = lane / LPH;
    float adst_h = g_adst[(size_t)d * H + head];

    float m = -INFINITY, s = 0.f;
    float acc[VPL];
#pragma unroll
    for (int v = 0; v < VPL; v++) acc[v] = 0.f;

    int lo = g_row[d], hi = g_row[d + 1];
    for (int i = lo; i < hi; i++) {
        int src = g_csr[i];
        float e = g_asrc[(size_t)src * H + head] + adst_h;
        e = (e > 0.f) ? e : 0.2f * e;
        if (e > m) {
            float corr = __expf(m - e);   // exp(-inf)=0 on first edge
            s *= corr;
#pragma unroll
            for (int v = 0; v < VPL; v++) acc[v] *= corr;
            m = e;
        }
        float wgt = __expf(e - m);
        s += wgt;
        const float* row = g_xp + (size_t)src * HC + lane * VPL;
        float vals[VPL];
        if constexpr (VPL == 4) {
            float4 t = *reinterpret_cast<const float4*>(row);
            vals[0] = t.x; vals[1] = t.y; vals[2] = t.z; vals[3] = t.w;
        } else if constexpr (VPL == 2) {
            float2 t = *reinterpret_cast<const float2*>(row);
            vals[0] = t.x; vals[1] = t.y;
        } else {
#pragma unroll
            for (int v = 0; v < VPL; v++) vals[v] = row[v];
        }
#pragma unroll
        for (int v = 0; v < VPL; v++) acc[v] += wgt * vals[v];
    }
    float inv = 1.f / (s + 1e-16f);
#pragma unroll
    for (int v = 0; v < VPL; v++) {
        float o = acc[v] * inv + bias[lane * VPL + v];
        if (DO_ELU) o = (o > 0.f) ? o : expm1f(o);
        g_h[(size_t)d * HC + lane * VPL + v] = o;
    }
}

// ---------------------------------------------------------------------------
// Layer 3 GEMM: xp3[N,10] = h[N,64] @ W3[64,10], padded to stride 16.
// One warp per row; also computes scalar asrc/adst.
// ---------------------------------------------------------------------------
__global__ void gemm3_kernel(const float* __restrict__ W3,
                             const float* __restrict__ a_s, const float* __restrict__ a_d,
                             int N) {
    __shared__ float Ws[64 * 10];
    __shared__ float as_s[10], ad_s[10];
    int t = threadIdx.x;
    for (int i = t; i < 640; i += blockDim.x) Ws[i] = W3[i];
    if (t < 10) { as_s[t] = a_s[t]; ad_s[t] = a_d[t]; }
    __syncthreads();

    int r = (blockIdx.x * blockDim.x + t) >> 5;
    int lane = t & 31;
    if (r >= N) return;
    float h0 = g_h[(size_t)r * 64 + lane];
    float h1 = g_h[(size_t)r * 64 + 32 + lane];
    float p[10];
#pragma unroll
    for (int c = 0; c < 10; c++)
        p[c] = h0 * Ws[lane * 10 + c] + h1 * Ws[(lane + 32) * 10 + c];
#pragma unroll
    for (int c = 0; c < 10; c++) {
#pragma unroll
        for (int off = 16; off >= 1; off >>= 1)
            p[c] += __shfl_xor_sync(0xFFFFFFFFu, p[c], off);
    }
    if (lane == 0) {
        float ss = 0.f, sd = 0.f;
#pragma unroll
        for (int c = 0; c < 10; c++) {
            g_xp[(size_t)r * 16 + c] = p[c];
            ss += p[c] * as_s[c];
            sd += p[c] * ad_s[c];
        }
        g_asrc[r] = ss;
        g_adst[r] = sd;
    }
}

// ---------------------------------------------------------------------------
// Layer 3 aggregation + log_softmax. One thread per destination.
// ---------------------------------------------------------------------------
__global__ void aggregate3_kernel(const float* __restrict__ bias,
                                  float* __restrict__ out, int N) {
    int d = blockIdx.x * blockDim.x + threadIdx.x;
    if (d >= N) return;
    float adst_d = g_adst[d];
    float m = -INFINITY, s = 0.f;
    float acc[10];
#pragma unroll
    for (int c = 0; c < 10; c++) acc[c] = 0.f;

    int lo = g_row[d], hi = g_row[d + 1];
    for (int i = lo; i < hi; i++) {
        int src = g_csr[i];
        float e = g_asrc[src] + adst_d;
        e = (e > 0.f) ? e : 0.2f * e;
        if (e > m) {
            float corr = __expf(m - e);
            s *= corr;
#pragma unroll
            for (int c = 0; c < 10; c++) acc[c] *= corr;
            m = e;
        }
        float wgt = __expf(e - m);
        s += wgt;
        const float* row = g_xp + (size_t)src * 16;
        float4 v0 = *reinterpret_cast<const float4*>(row);
        float4 v1 = *reinterpret_cast<const float4*>(row + 4);
        float2 v2 = *reinterpret_cast<const float2*>(row + 8);
        acc[0] += wgt * v0.x; acc[1] += wgt * v0.y; acc[2] += wgt * v0.z; acc[3] += wgt * v0.w;
        acc[4] += wgt * v1.x; acc[5] += wgt * v1.y; acc[6] += wgt * v1.z; acc[7] += wgt * v1.w;
        acc[8] += wgt * v2.x; acc[9] += wgt * v2.y;
    }
    float inv = 1.f / (s + 1e-16f);
    float logit[10];
    float mx = -INFINITY;
#pragma unroll
    for (int c = 0; c < 10; c++) {
        logit[c] = acc[c] * inv + bias[c];
        mx = fmaxf(mx, logit[c]);
    }
    float se = 0.f;
#pragma unroll
    for (int c = 0; c < 10; c++) se += __expf(logit[c] - mx);
    float lse = logf(se) + mx;
#pragma unroll
    for (int c = 0; c < 10; c++) out[(size_t)d * 10 + c] = logit[c] - lse;
}

// ---------------------------------------------------------------------------
// Launcher
// ---------------------------------------------------------------------------
extern "C" void kernel_launch(void* const* d_in, const int* in_sizes, int n_in,
                              void* d_out, int out_size) {
    const float* x   = (const float*)d_in[0];
    const void*  ei  = d_in[1];
    const float* W1 = (const float*)d_in[2];
    const float* a1s = (const float*)d_in[3];
    const float* a1d = (const float*)d_in[4];
    const float* b1 = (const float*)d_in[5];
    const float* W2 = (const float*)d_in[6];
    const float* a2s = (const float*)d_in[7];
    const float* a2d = (const float*)d_in[8];
    const float* b2 = (const float*)d_in[9];
    const float* W3 = (const float*)d_in[10];
    const float* a3s = (const float*)d_in[11];
    const float* a3d = (const float*)d_in[12];
    const float* b3 = (const float*)d_in[13];
    float* out = (float*)d_out;

    int N = in_sizes[0] / 256;
    int E = in_sizes[1] / 2;

    // --- Edge decode (dtype-agnostic) + CSR build ---
    detect_kernel<<<1, 1>>>(ei, N);
    convert_kernel<<<(E + 255) / 256, 256>>>(ei, E);
    init_deg_kernel<<<(N + 255) / 256, 256>>>(N);
    hist_kernel<<<(E + 255) / 256, 256>>>(E);
    scan_kernel<<<1, 1024>>>(N);
    scatter_kernel<<<(E + 255) / 256, 256>>>(E);

    int warp_blocks = (N + 7) / 8;  // warp-per-node kernels, 256 thr = 8 warps

    // --- Layer 1: 256 -> 8x16 ---
    gemm_kernel<256, 128, 64, 32, 8, 4><<<(N + 63) / 64, 256>>>(x, W1, N, 128);
    attn_kernel<8, 16><<<warp_blocks, 256>>>(a1s, a1d, N);
    aggregate_kernel<8, 16, true><<<warp_blocks, 256>>>(b1, N);

    // --- Layer 2: 128 -> 8x8 ---
    gemm_kernel<128, 64, 64, 32, 4, 4><<<(N + 63) / 64, 256>>>(nullptr, W2, N, 64);
    attn_kernel<8, 8><<<warp_blocks, 256>>>(a2s, a2d, N);
    aggregate_kernel<8, 8, true><<<warp_blocks, 256>>>(b2, N);

    // --- Layer 3: 64 -> 10, then log_softmax ---
    gemm3_kernel<<<warp_blocks, 256>>>(W3, a3s, a3d, N);
    aggregate3_kernel<<<(N + 255) / 256, 256>>>(b3, out, N);
}

// round 3
// speedup vs baseline: 1.5088x; 1.5088x over previous
#include <cuda_runtime.h>
#include <math.h>
#include <stdint.h>

// ---------------------------------------------------------------------------
// N=100000 nodes, F=256, E=1600000.
// Layer 1: 256 -> 8 heads x 16   (HC=128)
// Layer 2: 128 -> 8 heads x 8    (HC=64)
// Layer 3:  64 -> 1 head  x 10   (HC=10), then log_softmax
// ---------------------------------------------------------------------------
#define MAXN 100000
#define MAXE 1600000

__device__ __align__(16) float g_xp[MAXN * 128];   // transformed features
__device__ __align__(16) float g_h [MAXN * 128];   // layer activations
__device__ float g_asrc[MAXN * 8];
__device__ float g_adst[MAXN * 8];
__device__ int   g_srcbuf[MAXE];
__device__ int   g_dstbuf[MAXE];
__device__ int   g_deg[MAXN];
__device__ int   g_cursor[MAXN];
__device__ int   g_row[MAXN + 1];
__device__ int   g_csr[MAXE + MAXN];
__device__ int   g_bsum[1024];
__device__ int   g_boff[1024];
__device__ int   g_is64;

// ---------------------------------------------------------------------------
// f32x2 packed helpers (FFMA2 only reachable via PTX)
// ---------------------------------------------------------------------------
__device__ __forceinline__ unsigned long long pack2(float lo, float hi) {
    unsigned long long r;
    asm("mov.b64 %0, {%1, %2};" : "=l"(r) : "r"(__float_as_uint(lo)), "r"(__float_as_uint(hi)));
    return r;
}
__device__ __forceinline__ float2 unpack2(unsigned long long v) {
    unsigned int lo, hi;
    asm("mov.b64 {%0, %1}, %2;" : "=r"(lo), "=r"(hi) : "l"(v));
    return make_float2(__uint_as_float(lo), __uint_as_float(hi));
}
#define FMA2(d, a, b, c) \
    asm("fma.rn.f32x2 %0, %1, %2, %3;" : "=l"(d) : "l"(a), "l"(b), "l"(c))

// ---------------------------------------------------------------------------
// Edge dtype detection + conversion + degree histogram (fused)
// ---------------------------------------------------------------------------
__global__ void detect_kernel(const void* ei, int N) {
    const long long* p = (const long long*)ei;
    int ok = 1;
    for (int i = 0; i < 8; i++) {
        long long v = p[i];
        if (v < 0 || v >= (long long)N) ok = 0;
    }
    g_is64 = ok;
}

__global__ void init_deg_kernel(int N) {
    int i = blockIdx.x * blockDim.x + threadIdx.x;
    if (i < N) g_deg[i] = 1;   // self loop
}

__global__ void convert_hist_kernel(const void* ei, int E) {
    int e = blockIdx.x * blockDim.x + threadIdx.x;
    if (e >= E) return;
    int src, dst;
    if (g_is64) {
        const long long* p = (const long long*)ei;
        src = (int)p[e];
        dst = (int)p[(size_t)E + e];
    } else {
        const int* p = (const int*)ei;
        src = p[e];
        dst = p[(size_t)E + e];
    }
    g_srcbuf[e] = src;
    g_dstbuf[e] = dst;
    atomicAdd(&g_deg[dst], 1);
}

// ---------------------------------------------------------------------------
// Parallel exclusive scan (3 kernels), then seed self loops + cursors
// ---------------------------------------------------------------------------
__global__ void scan_blocks_kernel(int N) {
    int i = blockIdx.x * 256 + threadIdx.x;
    int v = (i < N) ? g_deg[i] : 0;
    int lane = threadIdx.x & 31, wid = threadIdx.x >> 5;
    int x = v;
#pragma unroll
    for (int off = 1; off < 32; off <<= 1) {
        int t = __shfl_up_sync(0xFFFFFFFFu, x, off);
        if (lane >= off) x += t;
    }
    __shared__ int wsum[8];
    if (lane == 31) wsum[wid] = x;
    __syncthreads();
    if (threadIdx.x == 0) {
        int run = 0;
#pragma unroll
        for (int w = 0; w < 8; w++) { int t = wsum[w]; wsum[w] = run; run += t; }
        g_bsum[blockIdx.x] = run;
    }
    __syncthreads();
    if (i < N) g_row[i] = x - v + wsum[wid];
}

__global__ void scan_top_kernel(int nb, int N) {
    int t = threadIdx.x;
    int v = (t < nb) ? g_bsum[t] : 0;
    int lane = t & 31, wid = t >> 5;
    int x = v;
#pragma unroll
    for (int off = 1; off < 32; off <<= 1) {
        int s = __shfl_up_sync(0xFFFFFFFFu, x, off);
        if (lane >= off) x += s;
    }
    __shared__ int wsum[32];
    if (lane == 31) wsum[wid] = x;
    __syncthreads();
    if (t == 0) {
        int run = 0;
#pragma unroll
        for (int w = 0; w < 32; w++) { int s = wsum[w]; wsum[w] = run; run += s; }
        g_row[N] = run;   // total edges incl. self loops
    }
    __syncthreads();
    if (t < nb) g_boff[t] = x - v + wsum[wid];
}

__global__ void scan_add_seed_kernel(int N) {
    int i = blockIdx.x * 256 + threadIdx.x;
    if (i >= N) return;
    int r = g_row[i] + g_boff[i >> 8];
    g_row[i] = r;
    g_csr[r] = i;          // self loop in slot 0
    g_cursor[i] = r + 1;
}

__global__ void scatter_kernel(int E) {
    int e = blockIdx.x * blockDim.x + threadIdx.x;
    if (e < E) {
        int pos = atomicAdd(&g_cursor[g_dstbuf[e]], 1);
        g_csr[pos] = g_srcbuf[e];
    }
}

// ---------------------------------------------------------------------------
// GEMM + fused attention logits.
// g_xp[N,KOUT] = A[N,KIN] @ W[KIN,KOUT]; asrc/adst via epilogue reduction.
// Tile: BM=128 x KOUT, BK=32, micro-tile 8x8, f32x2 packed FMA.
// ---------------------------------------------------------------------------
template <int KIN, int KOUT, int H, int C, bool READ_H>
__global__ void gemm_attn_kernel(const float* __restrict__ Ain,
                                 const float* __restrict__ W,
                                 const float* __restrict__ a_s,
                                 const float* __restrict__ a_d,
                                 int N) {
    constexpr int BM = 128, BK = 32, TM = 8, TN = 8;
    constexpr int TX = KOUT / TN;          // 16 (L1) / 8 (L2)
    constexpr int TY = BM / TM;            // 16
    constexpr int NT = TX * TY;            // 256 / 128
    constexpr int TPH = C / TN;            // threads per head: 2 (L1) / 1 (L2)

    __shared__ float As[BM][BK + 1];       // +1 pad: conflict-free broadcast
    __shared__ float Bs[BK][KOUT];
    __shared__ float s_as[KOUT], s_ad[KOUT];

    const float* A = READ_H ? g_h : Ain;
    int tid = threadIdx.x;
    int tx = tid % TX, ty = tid / TX;
    int row0 = blockIdx.x * BM;

    for (int i = tid; i < KOUT; i += NT) { s_as[i] = a_s[i]; s_ad[i] = a_d[i]; }

    unsigned long long acc2[TM][TN / 2];
#pragma unroll
    for (int i = 0; i < TM; i++)
#pragma unroll
        for (int p = 0; p < TN / 2; p++) acc2[i][p] = 0ull;   // {0.f, 0.f}

    for (int k0 = 0; k0 < KIN; k0 += BK) {
        // Load A tile (float4 gmem, 4x STS.32 conflict-free into padded As)
#pragma unroll
        for (int idx = tid; idx < BM * (BK / 4); idx += NT) {
            int k4 = idx % (BK / 4);
            int m  = idx / (BK / 4);
            int gr = row0 + m;
            float4 v = make_float4(0.f, 0.f, 0.f, 0.f);
            if (gr < N) v = *reinterpret_cast<const float4*>(&A[(size_t)gr * KIN + k0 + k4 * 4]);
            As[m][k4 * 4 + 0] = v.x;
            As[m][k4 * 4 + 1] = v.y;
            As[m][k4 * 4 + 2] = v.z;
            As[m][k4 * 4 + 3] = v.w;
        }
        // Load B tile
#pragma unroll
        for (int idx = tid; idx < BK * (KOUT / 4); idx += NT) {
            int n4 = idx % (KOUT / 4);
            int k  = idx / (KOUT / 4);
            *reinterpret_cast<float4*>(&Bs[k][n4 * 4]) =
                *reinterpret_cast<const float4*>(&W[(size_t)(k0 + k) * KOUT + n4 * 4]);
        }
        __syncthreads();
#pragma unroll
        for (int kk = 0; kk < BK; kk++) {
            // b: 8 contiguous floats = 4 packed f32x2 (no pack instrs needed)
            ulonglong2 bb0 = *reinterpret_cast<const ulonglong2*>(&Bs[kk][tx * TN]);
            ulonglong2 bb1 = *reinterpret_cast<const ulonglong2*>(&Bs[kk][tx * TN + 4]);
            unsigned long long b2[4] = {bb0.x, bb0.y, bb1.x, bb1.y};
#pragma unroll
            for (int i = 0; i < TM; i++) {
                float a = As[ty * TM + i][kk];
                unsigned long long a2 = pack2(a, a);
#pragma unroll
                for (int p = 0; p < TN / 2; p++)
                    FMA2(acc2[i][p], a2, b2[p], acc2[i][p]);
            }
        }
        __syncthreads();
    }

    // Epilogue: store xp, compute attention logits with pair reduction
#pragma unroll
    for (int i = 0; i < TM; i++) {
        int gr = row0 + ty * TM + i;
        float o[TN];
#pragma unroll
        for (int p = 0; p < TN / 2; p++) {
            float2 f = unpack2(acc2[i][p]);
            o[2 * p] = f.x;
            o[2 * p + 1] = f.y;
        }
        if (gr < N) {
            float4* dst = reinterpret_cast<float4*>(&g_xp[(size_t)gr * KOUT + tx * TN]);
            dst[0] = make_float4(o[0], o[1], o[2], o[3]);
            dst[1] = make_float4(o[4], o[5], o[6], o[7]);
        }
        float ps = 0.f, pd = 0.f;
#pragma unroll
        for (int j = 0; j < TN; j++) {
            ps += o[j] * s_as[tx * TN + j];
            pd += o[j] * s_ad[tx * TN + j];
        }
        if constexpr (TPH == 2) {
            ps += __shfl_xor_sync(0xFFFFFFFFu, ps, 1);
            pd += __shfl_xor_sync(0xFFFFFFFFu, pd, 1);
        }
        if (gr < N && (tx & (TPH - 1)) == 0) {
            int head = (tx * TN) / C;
            g_asrc[(size_t)gr * H + head] = ps;
            g_adst[(size_t)gr * H + head] = pd;
        }
    }
}

// ---------------------------------------------------------------------------
// Aggregation: warp-per-dst online softmax over CSR list, +bias, ELU.
// ---------------------------------------------------------------------------
template <int H, int C, bool DO_ELU>
__global__ void aggregate_kernel(const float* __restrict__ bias, int N) {
    constexpr int HC = H * C;
    constexpr int VPL = HC / 32;
    constexpr int LPH = C / VPL;
    int d = (blockIdx.x * blockDim.x + threadIdx.x) >> 5;
    int lane = threadIdx.x & 31;
    if (d >= N) return;
    int head = lane / LPH;
    float adst_h = g_adst[(size_t)d * H + head];

    float m = -INFINITY, s = 0.f;
    float acc[VPL];
#pragma unroll
    for (int v = 0; v < VPL; v++) acc[v] = 0.f;

    int lo = g_row[d], hi = g_row[d + 1];
    for (int i = lo; i < hi; i++) {
        int src = g_csr[i];
        float e = g_asrc[(size_t)src * H + head] + adst_h;
        e = (e > 0.f) ? e : 0.2f * e;
        if (e > m) {
            float corr = __expf(m - e);
            s *= corr;
#pragma unroll
            for (int v = 0; v < VPL; v++) acc[v] *= corr;
            m = e;
        }
        float wgt = __expf(e - m);
        s += wgt;
        const float* row = g_xp + (size_t)src * HC + lane * VPL;
        float vals[VPL];
        if constexpr (VPL == 4) {
            float4 t = *reinterpret_cast<const float4*>(row);
            vals[0] = t.x; vals[1] = t.y; vals[2] = t.z; vals[3] = t.w;
        } else {
            float2 t = *reinterpret_cast<const float2*>(row);
            vals[0] = t.x; vals[1] = t.y;
        }
#pragma unroll
        for (int v = 0; v < VPL; v++) acc[v] += wgt * vals[v];
    }
    float inv = 1.f / (s + 1e-16f);
#pragma unroll
    for (int v = 0; v < VPL; v++) {
        float o = acc[v] * inv + bias[lane * VPL + v];
        if (DO_ELU) o = (o > 0.f) ? o : expm1f(o);
        g_h[(size_t)d * HC + lane * VPL + v] = o;
    }
}

// ---------------------------------------------------------------------------
// Layer 3 GEMM: xp3[N,10] = h[N,64] @ W3[64,10] (stride 16) + attn logits.
// ---------------------------------------------------------------------------
__global__ void gemm3_kernel(const float* __restrict__ W3,
                             const float* __restrict__ a_s, const float* __restrict__ a_d,
                             int N) {
    __shared__ float Ws[64 * 10];
    __shared__ float as_s[10], ad_s[10];
    int t = threadIdx.x;
    for (int i = t; i < 640; i += blockDim.x) Ws[i] = W3[i];
    if (t < 10) { as_s[t] = a_s[t]; ad_s[t] = a_d[t]; }
    __syncthreads();

    int r = (blockIdx.x * blockDim.x + t) >> 5;
    int lane = t & 31;
    if (r >= N) return;
    float h0 = g_h[(size_t)r * 64 + lane];
    float h1 = g_h[(size_t)r * 64 + 32 + lane];
    float p[10];
#pragma unroll
    for (int c = 0; c < 10; c++)
        p[c] = h0 * Ws[lane * 10 + c] + h1 * Ws[(lane + 32) * 10 + c];
#pragma unroll
    for (int c = 0; c < 10; c++) {
#pragma unroll
        for (int off = 16; off >= 1; off >>= 1)
            p[c] += __shfl_xor_sync(0xFFFFFFFFu, p[c], off);
    }
    if (lane == 0) {
        float ss = 0.f, sd = 0.f;
#pragma unroll
        for (int c = 0; c < 10; c++) {
            g_xp[(size_t)r * 16 + c] = p[c];
            ss += p[c] * as_s[c];
            sd += p[c] * ad_s[c];
        }
        g_asrc[r] = ss;
        g_adst[r] = sd;
    }
}

// ---------------------------------------------------------------------------
// Layer 3 aggregation + log_softmax. One thread per destination.
// ---------------------------------------------------------------------------
__global__ void aggregate3_kernel(const float* __restrict__ bias,
                                  float* __restrict__ out, int N) {
    int d = blockIdx.x * blockDim.x + threadIdx.x;
    if (d >= N) return;
    float adst_d = g_adst[d];
    float m = -INFINITY, s = 0.f;
    float acc[10];
#pragma unroll
    for (int c = 0; c < 10; c++) acc[c] = 0.f;

    int lo = g_row[d], hi = g_row[d + 1];
    for (int i = lo; i < hi; i++) {
        int src = g_csr[i];
        float e = g_asrc[src] + adst_d;
        e = (e > 0.f) ? e : 0.2f * e;
        if (e > m) {
            float corr = __expf(m - e);
            s *= corr;
#pragma unroll
            for (int c = 0; c < 10; c++) acc[c] *= corr;
            m = e;
        }
        float wgt = __expf(e - m);
        s += wgt;
        const float* row = g_xp + (size_t)src * 16;
        float4 v0 = *reinterpret_cast<const float4*>(row);
        float4 v1 = *reinterpret_cast<const float4*>(row + 4);
        float2 v2 = *reinterpret_cast<const float2*>(row + 8);
        acc[0] += wgt * v0.x; acc[1] += wgt * v0.y; acc[2] += wgt * v0.z; acc[3] += wgt * v0.w;
        acc[4] += wgt * v1.x; acc[5] += wgt * v1.y; acc[6] += wgt * v1.z; acc[7] += wgt * v1.w;
        acc[8] += wgt * v2.x; acc[9] += wgt * v2.y;
    }
    float inv = 1.f / (s + 1e-16f);
    float logit[10];
    float mx = -INFINITY;
#pragma unroll
    for (int c = 0; c < 10; c++) {
        logit[c] = acc[c] * inv + bias[c];
        mx = fmaxf(mx, logit[c]);
    }
    float se = 0.f;
#pragma unroll
    for (int c = 0; c < 10; c++) se += __expf(logit[c] - mx);
    float lse = logf(se) + mx;
#pragma unroll
    for (int c = 0; c < 10; c++) out[(size_t)d * 10 + c] = logit[c] - lse;
}

// ---------------------------------------------------------------------------
// Launcher
// ---------------------------------------------------------------------------
extern "C" void kernel_launch(void* const* d_in, const int* in_sizes, int n_in,
                              void* d_out, int out_size) {
    const float* x   = (const float*)d_in[0];
    const void*  ei  = d_in[1];
    const float* W1 = (const float*)d_in[2];
    const float* a1s = (const float*)d_in[3];
    const float* a1d = (const float*)d_in[4];
    const float* b1 = (const float*)d_in[5];
    const float* W2 = (const float*)d_in[6];
    const float* a2s = (const float*)d_in[7];
    const float* a2d = (const float*)d_in[8];
    const float* b2 = (const float*)d_in[9];
    const float* W3 = (const float*)d_in[10];
    const float* a3s = (const float*)d_in[11];
    const float* a3d = (const float*)d_in[12];
    const float* b3 = (const float*)d_in[13];
    float* out = (float*)d_out;

    int N = in_sizes[0] / 256;
    int E = in_sizes[1] / 2;
    int nb = (N + 255) / 256;

    // --- Edge decode + CSR build ---
    detect_kernel<<<1, 1>>>(ei, N);
    init_deg_kernel<<<(N + 255) / 256, 256>>>(N);
    convert_hist_kernel<<<(E + 255) / 256, 256>>>(ei, E);
    scan_blocks_kernel<<<nb, 256>>>(N);
    scan_top_kernel<<<1, 1024>>>(nb, N);
    scan_add_seed_kernel<<<nb, 256>>>(N);
    scatter_kernel<<<(E + 255) / 256, 256>>>(E);

    int warp_blocks = (N + 7) / 8;
    int gemm_blocks = (N + 127) / 128;

    // --- Layer 1: 256 -> 8x16 ---
    gemm_attn_kernel<256, 128, 8, 16, false><<<gemm_blocks, 256>>>(x, W1, a1s, a1d, N);
    aggregate_kernel<8, 16, true><<<warp_blocks, 256>>>(b1, N);

    // --- Layer 2: 128 -> 8x8 ---
    gemm_attn_kernel<128, 64, 8, 8, true><<<gemm_blocks, 128>>>(nullptr, W2, a2s, a2d, N);
    aggregate_kernel<8, 8, true><<<warp_blocks, 256>>>(b2, N);

    // --- Layer 3: 64 -> 10, then log_softmax ---
    gemm3_kernel<<<warp_blocks, 256>>>(W3, a3s, a3d, N);
    aggregate3_kernel<<<(N + 255) / 256, 256>>>(b3, out, N);
}

// round 4
// speedup vs baseline: 2.0047x; 1.3287x over previous
#include <cuda_runtime.h>
#include <math.h>
#include <stdint.h>

// ---------------------------------------------------------------------------
// N=100000 nodes, F=256, E=1600000.
// Layer 1: 256 -> 8 heads x 16   (HC=128)
// Layer 2: 128 -> 8 heads x 8    (HC=64)
// Layer 3:  64 -> 1 head  x 10   (HC=10), then log_softmax
// ---------------------------------------------------------------------------
#define MAXN 100000
#define MAXE 1600000

__device__ __align__(16) float g_xp[MAXN * 128];   // transformed features
__device__ __align__(16) float g_h [MAXN * 128];   // layer activations
__device__ float g_asrc[MAXN * 8];
__device__ float g_adst[MAXN * 8];
__device__ int   g_srcbuf[MAXE];
__device__ int   g_dstbuf[MAXE];
__device__ int   g_deg[MAXN];
__device__ int   g_cursor[MAXN];
__device__ int   g_row[MAXN + 1];
__device__ int   g_csr[MAXE + MAXN];
__device__ int   g_bsum[1024];
__device__ int   g_boff[1024];
__device__ int   g_is64;

// ---------------------------------------------------------------------------
// f32x2 packed helpers (FFMA2 only reachable via PTX)
// ---------------------------------------------------------------------------
__device__ __forceinline__ unsigned long long pack2(float lo, float hi) {
    unsigned long long r;
    asm("mov.b64 %0, {%1, %2};" : "=l"(r) : "r"(__float_as_uint(lo)), "r"(__float_as_uint(hi)));
    return r;
}
__device__ __forceinline__ float2 unpack2(unsigned long long v) {
    unsigned int lo, hi;
    asm("mov.b64 {%0, %1}, %2;" : "=r"(lo), "=r"(hi) : "l"(v));
    return make_float2(__uint_as_float(lo), __uint_as_float(hi));
}
#define FMA2(d, a, b, c) \
    asm("fma.rn.f32x2 %0, %1, %2, %3;" : "=l"(d) : "l"(a), "l"(b), "l"(c))

__device__ __forceinline__ void cp_async16(uint32_t dst, const void* src) {
    asm volatile("cp.async.cg.shared.global [%0], [%1], 16;" :: "r"(dst), "l"(src));
}
#define CP_COMMIT() asm volatile("cp.async.commit_group;")
#define CP_WAIT0()  asm volatile("cp.async.wait_group 0;")

// ---------------------------------------------------------------------------
// Edge dtype detection + conversion + degree histogram
// ---------------------------------------------------------------------------
__global__ void detect_kernel(const void* ei, int N) {
    const long long* p = (const long long*)ei;
    int ok = 1;
    for (int i = 0; i < 8; i++) {
        long long v = p[i];
        if (v < 0 || v >= (long long)N) ok = 0;
    }
    g_is64 = ok;
}

__global__ void init_deg_kernel(int N) {
    int i = blockIdx.x * blockDim.x + threadIdx.x;
    if (i < N) g_deg[i] = 1;   // self loop
}

__global__ void convert_hist_kernel(const void* ei, int E) {
    int e = blockIdx.x * blockDim.x + threadIdx.x;
    if (e >= E) return;
    int src, dst;
    if (g_is64) {
        const long long* p = (const long long*)ei;
        src = (int)p[e];
        dst = (int)p[(size_t)E + e];
    } else {
        const int* p = (const int*)ei;
        src = p[e];
        dst = p[(size_t)E + e];
    }
    g_srcbuf[e] = src;
    g_dstbuf[e] = dst;
    atomicAdd(&g_deg[dst], 1);
}

// ---------------------------------------------------------------------------
// Parallel exclusive scan (3 kernels), seed self loops + cursors
// ---------------------------------------------------------------------------
__global__ void scan_blocks_kernel(int N) {
    int i = blockIdx.x * 256 + threadIdx.x;
    int v = (i < N) ? g_deg[i] : 0;
    int lane = threadIdx.x & 31, wid = threadIdx.x >> 5;
    int x = v;
#pragma unroll
    for (int off = 1; off < 32; off <<= 1) {
        int t = __shfl_up_sync(0xFFFFFFFFu, x, off);
        if (lane >= off) x += t;
    }
    __shared__ int wsum[8];
    if (lane == 31) wsum[wid] = x;
    __syncthreads();
    if (threadIdx.x == 0) {
        int run = 0;
#pragma unroll
        for (int w = 0; w < 8; w++) { int t = wsum[w]; wsum[w] = run; run += t; }
        g_bsum[blockIdx.x] = run;
    }
    __syncthreads();
    if (i < N) g_row[i] = x - v + wsum[wid];
}

__global__ void scan_top_kernel(int nb, int N) {
    int t = threadIdx.x;
    int v = (t < nb) ? g_bsum[t] : 0;
    int lane = t & 31, wid = t >> 5;
    int x = v;
#pragma unroll
    for (int off = 1; off < 32; off <<= 1) {
        int s = __shfl_up_sync(0xFFFFFFFFu, x, off);
        if (lane >= off) x += s;
    }
    __shared__ int wsum[32];
    if (lane == 31) wsum[wid] = x;
    __syncthreads();
    if (t == 0) {
        int run = 0;
#pragma unroll
        for (int w = 0; w < 32; w++) { int s = wsum[w]; wsum[w] = run; run += s; }
        g_row[N] = run;
    }
    __syncthreads();
    if (t < nb) g_boff[t] = x - v + wsum[wid];
}

__global__ void scan_add_seed_kernel(int N) {
    int i = blockIdx.x * 256 + threadIdx.x;
    if (i >= N) return;
    int r = g_row[i] + g_boff[i >> 8];
    g_row[i] = r;
    g_csr[r] = i;          // self loop in slot 0
    g_cursor[i] = r + 1;
}

__global__ void scatter_kernel(int E) {
    int e = blockIdx.x * blockDim.x + threadIdx.x;
    if (e < E) {
        int pos = atomicAdd(&g_cursor[g_dstbuf[e]], 1);
        g_csr[pos] = g_srcbuf[e];
    }
}

// ---------------------------------------------------------------------------
// GEMM + fused attention logits, cp.async double-buffered, f32x2 FMA.
// g_xp[N,KOUT] = A[N,KIN] @ W[KIN,KOUT]; asrc/adst via epilogue reduction.
// BM=128, BK=16, micro-tile 8x8.
// ---------------------------------------------------------------------------
template <int KIN, int KOUT, int H, int C, bool READ_H>
__global__ void gemm_attn_kernel(const float* __restrict__ Ain,
                                 const float* __restrict__ W,
                                 const float* __restrict__ a_s,
                                 const float* __restrict__ a_d,
                                 int N) {
    constexpr int BM = 128, BK = 16, TM = 8, TN = 8;
    constexpr int TX = KOUT / TN;          // 16 (L1) / 8 (L2)
    constexpr int TY = BM / TM;            // 16
    constexpr int NT = TX * TY;            // 256 / 128
    constexpr int TPH = C / TN;            // 2 (L1) / 1 (L2)
    constexpr int SA = BK + 4;             // A row stride (16B-aligned)
    constexpr int T  = KIN / BK;

    __shared__ float As[2][BM][SA];
    __shared__ float Bs[2][BK][KOUT];
    __shared__ float s_as[KOUT], s_ad[KOUT];

    const float* A = READ_H ? g_h : Ain;
    int tid = threadIdx.x;
    int tx = tid % TX, ty = tid / TX;
    int row0 = blockIdx.x * BM;

    for (int i = tid; i < KOUT; i += NT) { s_as[i] = a_s[i]; s_ad[i] = a_d[i]; }

    auto load_tile = [&](int t, int b) {
        int k0 = t * BK;
#pragma unroll
        for (int idx = tid; idx < BM * (BK / 4); idx += NT) {
            int k4 = idx % (BK / 4);
            int m  = idx / (BK / 4);
            int gr = min(row0 + m, N - 1);
            cp_async16((uint32_t)__cvta_generic_to_shared(&As[b][m][k4 * 4]),
                       &A[(size_t)gr * KIN + k0 + k4 * 4]);
        }
#pragma unroll
        for (int idx = tid; idx < BK * (KOUT / 4); idx += NT) {
            int n4 = idx % (KOUT / 4);
            int k  = idx / (KOUT / 4);
            cp_async16((uint32_t)__cvta_generic_to_shared(&Bs[b][k][n4 * 4]),
                       &W[(size_t)(k0 + k) * KOUT + n4 * 4]);
        }
        CP_COMMIT();
    };

    unsigned long long acc2[TM][TN / 2];
#pragma unroll
    for (int i = 0; i < TM; i++)
#pragma unroll
        for (int p = 0; p < TN / 2; p++) acc2[i][p] = 0ull;

    load_tile(0, 0);
    CP_WAIT0();
    __syncthreads();

    for (int t = 0; t < T; t++) {
        if (t + 1 < T) load_tile(t + 1, (t + 1) & 1);
        int b = t & 1;
#pragma unroll
        for (int kk = 0; kk < BK; kk++) {
            ulonglong2 bb0 = *reinterpret_cast<const ulonglong2*>(&Bs[b][kk][tx * TN]);
            ulonglong2 bb1 = *reinterpret_cast<const ulonglong2*>(&Bs[b][kk][tx * TN + 4]);
            unsigned long long b2[4] = {bb0.x, bb0.y, bb1.x, bb1.y};
#pragma unroll
            for (int i = 0; i < TM; i++) {
                float a = As[b][ty * TM + i][kk];
                unsigned long long a2 = pack2(a, a);
#pragma unroll
                for (int p = 0; p < TN / 2; p++)
                    FMA2(acc2[i][p], a2, b2[p], acc2[i][p]);
            }
        }
        if (t + 1 < T) {
            CP_WAIT0();
            __syncthreads();
        }
    }

    // Epilogue: store xp, fused attention logits
#pragma unroll
    for (int i = 0; i < TM; i++) {
        int gr = row0 + ty * TM + i;
        float o[TN];
#pragma unroll
        for (int p = 0; p < TN / 2; p++) {
            float2 f = unpack2(acc2[i][p]);
            o[2 * p] = f.x;
            o[2 * p + 1] = f.y;
        }
        if (gr < N) {
            float4* dst = reinterpret_cast<float4*>(&g_xp[(size_t)gr * KOUT + tx * TN]);
            dst[0] = make_float4(o[0], o[1], o[2], o[3]);
            dst[1] = make_float4(o[4], o[5], o[6], o[7]);
        }
        float ps = 0.f, pd = 0.f;
#pragma unroll
        for (int j = 0; j < TN; j++) {
            ps += o[j] * s_as[tx * TN + j];
            pd += o[j] * s_ad[tx * TN + j];
        }
        if constexpr (TPH == 2) {
            ps += __shfl_xor_sync(0xFFFFFFFFu, ps, 1);
            pd += __shfl_xor_sync(0xFFFFFFFFu, pd, 1);
        }
        if (gr < N && (tx & (TPH - 1)) == 0) {
            int head = (tx * TN) / C;
            g_asrc[(size_t)gr * H + head] = ps;
            g_adst[(size_t)gr * H + head] = pd;
        }
    }
}

// ---------------------------------------------------------------------------
// Aggregation v2: warp-per-dst, two-pass softmax.
// Pass 1: parallel max(asrc) across head-group lanes (LeakyReLU monotone =>
//         m = lrelu(max asrc + adst) exactly). Pass 2: branch-free exp+gather.
// ---------------------------------------------------------------------------
template <int H, int C, bool DO_ELU>
__global__ void aggregate_kernel(const float* __restrict__ bias, int N) {
    constexpr int HC = H * C;
    constexpr int VPL = HC / 32;
    constexpr int LPH = C / VPL;       // lanes per head
    int d = (blockIdx.x * blockDim.x + threadIdx.x) >> 5;
    int lane = threadIdx.x & 31;
    if (d >= N) return;
    int head = lane / LPH;
    int sub  = lane % LPH;
    float adst_h = g_adst[(size_t)d * H + head];

    int lo = g_row[d], hi = g_row[d + 1];

    // Pass 1: max over asrc[src][head], split across head-group lanes
    float ma = -INFINITY;
    for (int i = lo + sub; i < hi; i += LPH)
        ma = fmaxf(ma, g_asrc[(size_t)g_csr[i] * H + head]);
#pragma unroll
    for (int off = LPH / 2; off >= 1; off >>= 1)
        ma = fmaxf(ma, __shfl_xor_sync(0xFFFFFFFFu, ma, off));
    float em = ma + adst_h;
    float m = (em > 0.f) ? em : 0.2f * em;

    // Pass 2: branch-free weighted gather
    float s = 0.f;
    float acc[VPL];
#pragma unroll
    for (int v = 0; v < VPL; v++) acc[v] = 0.f;

#pragma unroll 2
    for (int i = lo; i < hi; i++) {
        int src = g_csr[i];
        float e = g_asrc[(size_t)src * H + head] + adst_h;
        e = (e > 0.f) ? e : 0.2f * e;
        float wgt = __expf(e - m);
        s += wgt;
        const float* row = g_xp + (size_t)src * HC + lane * VPL;
        if constexpr (VPL == 4) {
            float4 t = *reinterpret_cast<const float4*>(row);
            acc[0] += wgt * t.x; acc[1] += wgt * t.y;
            acc[2] += wgt * t.z; acc[3] += wgt * t.w;
        } else {
            float2 t = *reinterpret_cast<const float2*>(row);
            acc[0] += wgt * t.x; acc[1] += wgt * t.y;
        }
    }
    float inv = 1.f / (s + 1e-16f);
#pragma unroll
    for (int v = 0; v < VPL; v++) {
        float o = acc[v] * inv + bias[lane * VPL + v];
        if (DO_ELU) o = (o > 0.f) ? o : expm1f(o);
        g_h[(size_t)d * HC + lane * VPL + v] = o;
    }
}

// ---------------------------------------------------------------------------
// Layer 3 GEMM: xp3[N,10] = h[N,64] @ W3[64,10] (stride 16) + attn logits.
// ---------------------------------------------------------------------------
__global__ void gemm3_kernel(const float* __restrict__ W3,
                             const float* __restrict__ a_s, const float* __restrict__ a_d,
                             int N) {
    __shared__ float Ws[64 * 10];
    __shared__ float as_s[10], ad_s[10];
    int t = threadIdx.x;
    for (int i = t; i < 640; i += blockDim.x) Ws[i] = W3[i];
    if (t < 10) { as_s[t] = a_s[t]; ad_s[t] = a_d[t]; }
    __syncthreads();

    int r = (blockIdx.x * blockDim.x + t) >> 5;
    int lane = t & 31;
    if (r >= N) return;
    float h0 = g_h[(size_t)r * 64 + lane];
    float h1 = g_h[(size_t)r * 64 + 32 + lane];
    float p[10];
#pragma unroll
    for (int c = 0; c < 10; c++)
        p[c] = h0 * Ws[lane * 10 + c] + h1 * Ws[(lane + 32) * 10 + c];
#pragma unroll
    for (int c = 0; c < 10; c++) {
#pragma unroll
        for (int off = 16; off >= 1; off >>= 1)
            p[c] += __shfl_xor_sync(0xFFFFFFFFu, p[c], off);
    }
    if (lane == 0) {
        float ss = 0.f, sd = 0.f;
#pragma unroll
        for (int c = 0; c < 10; c++) {
            g_xp[(size_t)r * 16 + c] = p[c];
            ss += p[c] * as_s[c];
            sd += p[c] * ad_s[c];
        }
        g_asrc[r] = ss;
        g_adst[r] = sd;
    }
}

// ---------------------------------------------------------------------------
// Layer 3 aggregation + log_softmax. One thread per destination, two-pass.
// ---------------------------------------------------------------------------
__global__ void aggregate3_kernel(const float* __restrict__ bias,
                                  float* __restrict__ out, int N) {
    int d = blockIdx.x * blockDim.x + threadIdx.x;
    if (d >= N) return;
    float adst_d = g_adst[d];
    int lo = g_row[d], hi = g_row[d + 1];

    float ma = -INFINITY;
    for (int i = lo; i < hi; i++)
        ma = fmaxf(ma, g_asrc[g_csr[i]]);
    float em = ma + adst_d;
    float m = (em > 0.f) ? em : 0.2f * em;

    float s = 0.f;
    float acc[10];
#pragma unroll
    for (int c = 0; c < 10; c++) acc[c] = 0.f;

    for (int i = lo; i < hi; i++) {
        int src = g_csr[i];
        float e = g_asrc[src] + adst_d;
        e = (e > 0.f) ? e : 0.2f * e;
        float wgt = __expf(e - m);
        s += wgt;
        const float* row = g_xp + (size_t)src * 16;
        float4 v0 = *reinterpret_cast<const float4*>(row);
        float4 v1 = *reinterpret_cast<const float4*>(row + 4);
        float2 v2 = *reinterpret_cast<const float2*>(row + 8);
        acc[0] += wgt * v0.x; acc[1] += wgt * v0.y; acc[2] += wgt * v0.z; acc[3] += wgt * v0.w;
        acc[4] += wgt * v1.x; acc[5] += wgt * v1.y; acc[6] += wgt * v1.z; acc[7] += wgt * v1.w;
        acc[8] += wgt * v2.x; acc[9] += wgt * v2.y;
    }
    float inv = 1.f / (s + 1e-16f);
    float logit[10];
    float mx = -INFINITY;
#pragma unroll
    for (int c = 0; c < 10; c++) {
        logit[c] = acc[c] * inv + bias[c];
        mx = fmaxf(mx, logit[c]);
    }
    float se = 0.f;
#pragma unroll
    for (int c = 0; c < 10; c++) se += __expf(logit[c] - mx);
    float lse = logf(se) + mx;
#pragma unroll
    for (int c = 0; c < 10; c++) out[(size_t)d * 10 + c] = logit[c] - lse;
}

// ---------------------------------------------------------------------------
// Launcher
// ---------------------------------------------------------------------------
extern "C" void kernel_launch(void* const* d_in, const int* in_sizes, int n_in,
                              void* d_out, int out_size) {
    const float* x   = (const float*)d_in[0];
    const void*  ei  = d_in[1];
    const float* W1 = (const float*)d_in[2];
    const float* a1s = (const float*)d_in[3];
    const float* a1d = (const float*)d_in[4];
    const float* b1 = (const float*)d_in[5];
    const float* W2 = (const float*)d_in[6];
    const float* a2s = (const float*)d_in[7];
    const float* a2d = (const float*)d_in[8];
    const float* b2 = (const float*)d_in[9];
    const float* W3 = (const float*)d_in[10];
    const float* a3s = (const float*)d_in[11];
    const float* a3d = (const float*)d_in[12];
    const float* b3 = (const float*)d_in[13];
    float* out = (float*)d_out;

    int N = in_sizes[0] / 256;
    int E = in_sizes[1] / 2;
    int nb = (N + 255) / 256;

    // --- Edge decode + CSR build ---
    detect_kernel<<<1, 1>>>(ei, N);
    init_deg_kernel<<<(N + 255) / 256, 256>>>(N);
    convert_hist_kernel<<<(E + 255) / 256, 256>>>(ei, E);
    scan_blocks_kernel<<<nb, 256>>>(N);
    scan_top_kernel<<<1, 1024>>>(nb, N);
    scan_add_seed_kernel<<<nb, 256>>>(N);
    scatter_kernel<<<(E + 255) / 256, 256>>>(E);

    int warp_blocks = (N + 7) / 8;
    int gemm_blocks = (N + 127) / 128;

    // --- Layer 1: 256 -> 8x16 ---
    gemm_attn_kernel<256, 128, 8, 16, false><<<gemm_blocks, 256>>>(x, W1, a1s, a1d, N);
    aggregate_kernel<8, 16, true><<<warp_blocks, 256>>>(b1, N);

    // --- Layer 2: 128 -> 8x8 ---
    gemm_attn_kernel<128, 64, 8, 8, true><<<gemm_blocks, 128>>>(nullptr, W2, a2s, a2d, N);
    aggregate_kernel<8, 8, true><<<warp_blocks, 256>>>(b2, N);

    // --- Layer 3: 64 -> 10, then log_softmax ---
    gemm3_kernel<<<warp_blocks, 256>>>(W3, a3s, a3d, N);
    aggregate3_kernel<<<(N + 255) / 256, 256>>>(b3, out, N);
}

// round 5
// speedup vs baseline: 2.8358x; 1.4146x over previous
#include <cuda_runtime.h>
#include <math.h>
#include <stdint.h>

// ---------------------------------------------------------------------------
// N=100000 nodes, F=256, E=1600000.
// Layer 1: 256 -> 8 heads x 16   (HC=128)
// Layer 2: 128 -> 8 heads x 8    (HC=64)
// Layer 3:  64 -> 1 head  x 10   (HC=10), then log_softmax
// ---------------------------------------------------------------------------
#define MAXN 100000
#define MAXE 1600000

__device__ __align__(16) float g_xp[MAXN * 128];   // transformed features
__device__ __align__(16) float g_h [MAXN * 128];   // layer activations
__device__ float g_asrc[MAXN * 8];
__device__ float g_adst[MAXN * 8];
__device__ int   g_srcbuf[MAXE];
__device__ int   g_dstbuf[MAXE];
__device__ int   g_deg[MAXN];
__device__ int   g_cursor[MAXN];
__device__ int   g_row[MAXN + 1];
__device__ int   g_csr[MAXE + MAXN];
__device__ int   g_bsum[1024];
__device__ int   g_boff[1024];
__device__ int   g_is64;

// ---------------------------------------------------------------------------
// PTX helpers
// ---------------------------------------------------------------------------
__device__ __forceinline__ void cp_async16(uint32_t dst, const void* src) {
    asm volatile("cp.async.cg.shared.global [%0], [%1], 16;" :: "r"(dst), "l"(src));
}
#define CP_COMMIT() asm volatile("cp.async.commit_group;")
#define CP_WAIT0()  asm volatile("cp.async.wait_group 0;")

__device__ __forceinline__ uint32_t f2tf(float f) {
    uint32_t r;
    asm("cvt.rna.tf32.f32 %0, %1;" : "=r"(r) : "f"(f));
    return r;
}

__device__ __forceinline__ void mma_tf32(float& d0, float& d1, float& d2, float& d3,
                                         uint32_t a0, uint32_t a1, uint32_t a2, uint32_t a3,
                                         uint32_t b0, uint32_t b1) {
    asm("mma.sync.aligned.m16n8k8.row.col.f32.tf32.tf32.f32 "
        "{%0,%1,%2,%3}, {%4,%5,%6,%7}, {%8,%9}, {%0,%1,%2,%3};"
        : "+f"(d0), "+f"(d1), "+f"(d2), "+f"(d3)
        : "r"(a0), "r"(a1), "r"(a2), "r"(a3), "r"(b0), "r"(b1));
}

// ---------------------------------------------------------------------------
// Edge dtype detection + conversion + degree histogram
// ---------------------------------------------------------------------------
__global__ void detect_kernel(const void* ei, int N) {
    const long long* p = (const long long*)ei;
    int ok = 1;
    for (int i = 0; i < 8; i++) {
        long long v = p[i];
        if (v < 0 || v >= (long long)N) ok = 0;
    }
    g_is64 = ok;
}

__global__ void init_deg_kernel(int N) {
    int i = blockIdx.x * blockDim.x + threadIdx.x;
    if (i < N) g_deg[i] = 1;   // self loop
}

__global__ void convert_hist_kernel(const void* ei, int E) {
    int e = blockIdx.x * blockDim.x + threadIdx.x;
    if (e >= E) return;
    int src, dst;
    if (g_is64) {
        const long long* p = (const long long*)ei;
        src = (int)p[e];
        dst = (int)p[(size_t)E + e];
    } else {
        const int* p = (const int*)ei;
        src = p[e];
        dst = p[(size_t)E + e];
    }
    g_srcbuf[e] = src;
    g_dstbuf[e] = dst;
    atomicAdd(&g_deg[dst], 1);
}

// ---------------------------------------------------------------------------
// Parallel exclusive scan (3 kernels), seed self loops + cursors
// ---------------------------------------------------------------------------
__global__ void scan_blocks_kernel(int N) {
    int i = blockIdx.x * 256 + threadIdx.x;
    int v = (i < N) ? g_deg[i] : 0;
    int lane = threadIdx.x & 31, wid = threadIdx.x >> 5;
    int x = v;
#pragma unroll
    for (int off = 1; off < 32; off <<= 1) {
        int t = __shfl_up_sync(0xFFFFFFFFu, x, off);
        if (lane >= off) x += t;
    }
    __shared__ int wsum[8];
    if (lane == 31) wsum[wid] = x;
    __syncthreads();
    if (threadIdx.x == 0) {
        int run = 0;
#pragma unroll
        for (int w = 0; w < 8; w++) { int t = wsum[w]; wsum[w] = run; run += t; }
        g_bsum[blockIdx.x] = run;
    }
    __syncthreads();
    if (i < N) g_row[i] = x - v + wsum[wid];
}

__global__ void scan_top_kernel(int nb, int N) {
    int t = threadIdx.x;
    int v = (t < nb) ? g_bsum[t] : 0;
    int lane = t & 31, wid = t >> 5;
    int x = v;
#pragma unroll
    for (int off = 1; off < 32; off <<= 1) {
        int s = __shfl_up_sync(0xFFFFFFFFu, x, off);
        if (lane >= off) x += s;
    }
    __shared__ int wsum[32];
    if (lane == 31) wsum[wid] = x;
    __syncthreads();
    if (t == 0) {
        int run = 0;
#pragma unroll
        for (int w = 0; w < 32; w++) { int s = wsum[w]; wsum[w] = run; run += s; }
        g_row[N] = run;
    }
    __syncthreads();
    if (t < nb) g_boff[t] = x - v + wsum[wid];
}

__global__ void scan_add_seed_kernel(int N) {
    int i = blockIdx.x * 256 + threadIdx.x;
    if (i >= N) return;
    int r = g_row[i] + g_boff[i >> 8];
    g_row[i] = r;
    g_csr[r] = i;          // self loop in slot 0
    g_cursor[i] = r + 1;
}

__global__ void scatter_kernel(int E) {
    int e = blockIdx.x * blockDim.x + threadIdx.x;
    if (e < E) {
        int pos = atomicAdd(&g_cursor[g_dstbuf[e]], 1);
        g_csr[pos] = g_srcbuf[e];
    }
}

// ---------------------------------------------------------------------------
// Tensor-core GEMM (tf32 mma.sync) + fused attention logits.
// g_xp[N,KOUT] = A[N,KIN] @ W[KIN,KOUT]; asrc/adst via epilogue reduction.
// BM=128, BN=KOUT, BK=32, 8 warps in 4(M) x 2(N); warp tile 32 x (BN/2).
// Smem strides: A=36 (banks 4*gid+tig distinct), B=BN+8 (banks 8*tig+gid distinct).
// ---------------------------------------------------------------------------
template <int KIN, int KOUT, int H, int C, bool READ_H>
__global__ void gemm_mma_kernel(const float* __restrict__ Ain,
                                const float* __restrict__ W,
                                const float* __restrict__ a_s,
                                const float* __restrict__ a_d,
                                int N) {
    constexpr int BM = 128, BK = 32, BN = KOUT;
    constexpr int NT = 256;
    constexpr int SA = 36;             // A smem row stride (floats)
    constexpr int SB = BN + 8;         // B smem row stride (floats)
    constexpr int T  = KIN / BK;
    constexpr int BNW = BN / 2;        // warp N-span
    constexpr int NTILES = BNW / 8;
    constexpr int MTILES = 2;
    constexpr int NHL = BNW / C;       // heads per warp (4 in both layers)
    constexpr int AS_SZ = 2 * BM * SA;
    constexpr int BS_SZ = 2 * BK * SB;

    extern __shared__ float sm[];
    float* As  = sm;
    float* Bs  = sm + AS_SZ;
    float* s_as = sm + AS_SZ + BS_SZ;
    float* s_ad = s_as + BN;

    const float* A = READ_H ? g_h : Ain;
    int tid = threadIdx.x;
    int row0 = blockIdx.x * BM;

    for (int i = tid; i < BN; i += NT) { s_as[i] = a_s[i]; s_ad[i] = a_d[i]; }

    auto load_tile = [&](int t, int b) {
        int k0 = t * BK;
#pragma unroll
        for (int idx = tid; idx < BM * (BK / 4); idx += NT) {
            int m = idx >> 3, k4 = idx & 7;
            int gr = min(row0 + m, N - 1);
            cp_async16((uint32_t)__cvta_generic_to_shared(&As[b * BM * SA + m * SA + k4 * 4]),
                       &A[(size_t)gr * KIN + k0 + k4 * 4]);
        }
#pragma unroll
        for (int idx = tid; idx < BK * (BN / 4); idx += NT) {
            int k = idx / (BN / 4), n4 = idx % (BN / 4);
            cp_async16((uint32_t)__cvta_generic_to_shared(&Bs[b * BK * SB + k * SB + n4 * 4]),
                       &W[(size_t)(k0 + k) * KOUT + n4 * 4]);
        }
        CP_COMMIT();
    };

    int lane = tid & 31;
    int gid = lane >> 2, tig = lane & 3;
    int w = tid >> 5;
    int warp_n = w & 1, warp_m = w >> 1;
    int mbase = warp_m * 32;
    int nbase = warp_n * BNW;

    float acc[MTILES][NTILES][4];
#pragma unroll
    for (int mt = 0; mt < MTILES; mt++)
#pragma unroll
        for (int nt = 0; nt < NTILES; nt++)
#pragma unroll
            for (int q = 0; q < 4; q++) acc[mt][nt][q] = 0.f;

    load_tile(0, 0);
    CP_WAIT0();
    __syncthreads();

    for (int t = 0; t < T; t++) {
        if (t + 1 < T) load_tile(t + 1, (t + 1) & 1);
        int b = t & 1;
        const float* Ab = &As[b * BM * SA];
        const float* Bb = &Bs[b * BK * SB];
#pragma unroll
        for (int k8 = 0; k8 < BK / 8; k8++) {
            int kk = k8 * 8;
            uint32_t af[MTILES][4];
#pragma unroll
            for (int mt = 0; mt < MTILES; mt++) {
                const float* ar = &Ab[(mbase + mt * 16 + gid) * SA + kk + tig];
                af[mt][0] = f2tf(ar[0]);
                af[mt][1] = f2tf(ar[8 * SA]);
                af[mt][2] = f2tf(ar[4]);
                af[mt][3] = f2tf(ar[8 * SA + 4]);
            }
            uint32_t bf[NTILES][2];
#pragma unroll
            for (int nt = 0; nt < NTILES; nt++) {
                const float* br = &Bb[(kk + tig) * SB + nbase + nt * 8 + gid];
                bf[nt][0] = f2tf(br[0]);
                bf[nt][1] = f2tf(br[4 * SB]);
            }
#pragma unroll
            for (int mt = 0; mt < MTILES; mt++)
#pragma unroll
                for (int nt = 0; nt < NTILES; nt++)
                    mma_tf32(acc[mt][nt][0], acc[mt][nt][1], acc[mt][nt][2], acc[mt][nt][3],
                             af[mt][0], af[mt][1], af[mt][2], af[mt][3],
                             bf[nt][0], bf[nt][1]);
        }
        if (t + 1 < T) {
            CP_WAIT0();
            __syncthreads();
        }
    }

    // Epilogue: store xp, fused attention logits (asrc/adst per head)
#pragma unroll
    for (int mt = 0; mt < MTILES; mt++) {
        int r0 = row0 + mbase + mt * 16 + gid;
        int r1 = r0 + 8;
        float ps0[NHL], pd0[NHL], ps1[NHL], pd1[NHL];
#pragma unroll
        for (int hl = 0; hl < NHL; hl++) { ps0[hl] = pd0[hl] = ps1[hl] = pd1[hl] = 0.f; }
#pragma unroll
        for (int nt = 0; nt < NTILES; nt++) {
            int col = nbase + nt * 8 + 2 * tig;
            int hl = (nt * 8) / C;
            float d0 = acc[mt][nt][0], d1 = acc[mt][nt][1];
            float d2 = acc[mt][nt][2], d3 = acc[mt][nt][3];
            if (r0 < N) *reinterpret_cast<float2*>(&g_xp[(size_t)r0 * KOUT + col]) = make_float2(d0, d1);
            if (r1 < N) *reinterpret_cast<float2*>(&g_xp[(size_t)r1 * KOUT + col]) = make_float2(d2, d3);
            float w0 = s_as[col], w1 = s_as[col + 1];
            float v0 = s_ad[col], v1 = s_ad[col + 1];
            ps0[hl] += d0 * w0 + d1 * w1;
            pd0[hl] += d0 * v0 + d1 * v1;
            ps1[hl] += d2 * w0 + d3 * w1;
            pd1[hl] += d2 * v0 + d3 * v1;
        }
#pragma unroll
        for (int hl = 0; hl < NHL; hl++) {
            ps0[hl] += __shfl_xor_sync(0xFFFFFFFFu, ps0[hl], 1);
            ps0[hl] += __shfl_xor_sync(0xFFFFFFFFu, ps0[hl], 2);
            pd0[hl] += __shfl_xor_sync(0xFFFFFFFFu, pd0[hl], 1);
            pd0[hl] += __shfl_xor_sync(0xFFFFFFFFu, pd0[hl], 2);
            ps1[hl] += __shfl_xor_sync(0xFFFFFFFFu, ps1[hl], 1);
            ps1[hl] += __shfl_xor_sync(0xFFFFFFFFu, ps1[hl], 2);
            pd1[hl] += __shfl_xor_sync(0xFFFFFFFFu, pd1[hl], 1);
            pd1[hl] += __shfl_xor_sync(0xFFFFFFFFu, pd1[hl], 2);
        }
        if (tig == 0) {
#pragma unroll
            for (int hl = 0; hl < NHL; hl++) {
                int head = nbase / C + hl;
                if (r0 < N) {
                    g_asrc[(size_t)r0 * H + head] = ps0[hl];
                    g_adst[(size_t)r0 * H + head] = pd0[hl];
                }
                if (r1 < N) {
                    g_asrc[(size_t)r1 * H + head] = ps1[hl];
                    g_adst[(size_t)r1 * H + head] = pd1[hl];
                }
            }
        }
    }
}

// ---------------------------------------------------------------------------
// Aggregation: warp-per-dst, two-pass softmax (max exact via LeakyReLU
// monotonicity), branch-free weighted gather.
// ---------------------------------------------------------------------------
template <int H, int C, bool DO_ELU>
__global__ void aggregate_kernel(const float* __restrict__ bias, int N) {
    constexpr int HC = H * C;
    constexpr int VPL = HC / 32;
    constexpr int LPH = C / VPL;       // lanes per head
    int d = (blockIdx.x * blockDim.x + threadIdx.x) >> 5;
    int lane = threadIdx.x & 31;
    if (d >= N) return;
    int head = lane / LPH;
    int sub  = lane % LPH;
    float adst_h = g_adst[(size_t)d * H + head];

    int lo = g_row[d], hi = g_row[d + 1];

    float ma = -INFINITY;
    for (int i = lo + sub; i < hi; i += LPH)
        ma = fmaxf(ma, g_asrc[(size_t)g_csr[i] * H + head]);
#pragma unroll
    for (int off = LPH / 2; off >= 1; off >>= 1)
        ma = fmaxf(ma, __shfl_xor_sync(0xFFFFFFFFu, ma, off));
    float em = ma + adst_h;
    float m = (em > 0.f) ? em : 0.2f * em;

    float s = 0.f;
    float acc[VPL];
#pragma unroll
    for (int v = 0; v < VPL; v++) acc[v] = 0.f;

#pragma unroll 2
    for (int i = lo; i < hi; i++) {
        int src = g_csr[i];
        float e = g_asrc[(size_t)src * H + head] + adst_h;
        e = (e > 0.f) ? e : 0.2f * e;
        float wgt = __expf(e - m);
        s += wgt;
        const float* row = g_xp + (size_t)src * HC + lane * VPL;
        if constexpr (VPL == 4) {
            float4 t = *reinterpret_cast<const float4*>(row);
            acc[0] += wgt * t.x; acc[1] += wgt * t.y;
            acc[2] += wgt * t.z; acc[3] += wgt * t.w;
        } else {
            float2 t = *reinterpret_cast<const float2*>(row);
            acc[0] += wgt * t.x; acc[1] += wgt * t.y;
        }
    }
    float inv = 1.f / (s + 1e-16f);
#pragma unroll
    for (int v = 0; v < VPL; v++) {
        float o = acc[v] * inv + bias[lane * VPL + v];
        if (DO_ELU) o = (o > 0.f) ? o : expm1f(o);
        g_h[(size_t)d * HC + lane * VPL + v] = o;
    }
}

// ---------------------------------------------------------------------------
// Layer 3 GEMM: xp3[N,10] = h[N,64] @ W3[64,10] (stride 16) + attn logits.
// ---------------------------------------------------------------------------
__global__ void gemm3_kernel(const float* __restrict__ W3,
                             const float* __restrict__ a_s, const float* __restrict__ a_d,
                             int N) {
    __shared__ float Ws[64 * 10];
    __shared__ float as_s[10], ad_s[10];
    int t = threadIdx.x;
    for (int i = t; i < 640; i += blockDim.x) Ws[i] = W3[i];
    if (t < 10) { as_s[t] = a_s[t]; ad_s[t] = a_d[t]; }
    __syncthreads();

    int r = (blockIdx.x * blockDim.x + t) >> 5;
    int lane = t & 31;
    if (r >= N) return;
    float h0 = g_h[(size_t)r * 64 + lane];
    float h1 = g_h[(size_t)r * 64 + 32 + lane];
    float p[10];
#pragma unroll
    for (int c = 0; c < 10; c++)
        p[c] = h0 * Ws[lane * 10 + c] + h1 * Ws[(lane + 32) * 10 + c];
#pragma unroll
    for (int c = 0; c < 10; c++) {
#pragma unroll
        for (int off = 16; off >= 1; off >>= 1)
            p[c] += __shfl_xor_sync(0xFFFFFFFFu, p[c], off);
    }
    if (lane == 0) {
        float ss = 0.f, sd = 0.f;
#pragma unroll
        for (int c = 0; c < 10; c++) {
            g_xp[(size_t)r * 16 + c] = p[c];
            ss += p[c] * as_s[c];
            sd += p[c] * ad_s[c];
        }
        g_asrc[r] = ss;
        g_adst[r] = sd;
    }
}

// ---------------------------------------------------------------------------
// Layer 3 aggregation + log_softmax. One thread per destination, two-pass.
// ---------------------------------------------------------------------------
__global__ void aggregate3_kernel(const float* __restrict__ bias,
                                  float* __restrict__ out, int N) {
    int d = blockIdx.x * blockDim.x + threadIdx.x;
    if (d >= N) return;
    float adst_d = g_adst[d];
    int lo = g_row[d], hi = g_row[d + 1];

    float ma = -INFINITY;
    for (int i = lo; i < hi; i++)
        ma = fmaxf(ma, g_asrc[g_csr[i]]);
    float em = ma + adst_d;
    float m = (em > 0.f) ? em : 0.2f * em;

    float s = 0.f;
    float acc[10];
#pragma unroll
    for (int c = 0; c < 10; c++) acc[c] = 0.f;

    for (int i = lo; i < hi; i++) {
        int src = g_csr[i];
        float e = g_asrc[src] + adst_d;
        e = (e > 0.f) ? e : 0.2f * e;
        float wgt = __expf(e - m);
        s += wgt;
        const float* row = g_xp + (size_t)src * 16;
        float4 v0 = *reinterpret_cast<const float4*>(row);
        float4 v1 = *reinterpret_cast<const float4*>(row + 4);
        float2 v2 = *reinterpret_cast<const float2*>(row + 8);
        acc[0] += wgt * v0.x; acc[1] += wgt * v0.y; acc[2] += wgt * v0.z; acc[3] += wgt * v0.w;
        acc[4] += wgt * v1.x; acc[5] += wgt * v1.y; acc[6] += wgt * v1.z; acc[7] += wgt * v1.w;
        acc[8] += wgt * v2.x; acc[9] += wgt * v2.y;
    }
    float inv = 1.f / (s + 1e-16f);
    float logit[10];
    float mx = -INFINITY;
#pragma unroll
    for (int c = 0; c < 10; c++) {
        logit[c] = acc[c] * inv + bias[c];
        mx = fmaxf(mx, logit[c]);
    }
    float se = 0.f;
#pragma unroll
    for (int c = 0; c < 10; c++) se += __expf(logit[c] - mx);
    float lse = logf(se) + mx;
#pragma unroll
    for (int c = 0; c < 10; c++) out[(size_t)d * 10 + c] = logit[c] - lse;
}

// ---------------------------------------------------------------------------
// Launcher (CSR build forked onto a side stream, overlapped with GEMM1)
// ---------------------------------------------------------------------------
extern "C" void kernel_launch(void* const* d_in, const int* in_sizes, int n_in,
                              void* d_out, int out_size) {
    const float* x   = (const float*)d_in[0];
    const void*  ei  = d_in[1];
    const float* W1 = (const float*)d_in[2];
    const float* a1s = (const float*)d_in[3];
    const float* a1d = (const float*)d_in[4];
    const float* b1 = (const float*)d_in[5];
    const float* W2 = (const float*)d_in[6];
    const float* a2s = (const float*)d_in[7];
    const float* a2d = (const float*)d_in[8];
    const float* b2 = (const float*)d_in[9];
    const float* W3 = (const float*)d_in[10];
    const float* a3s = (const float*)d_in[11];
    const float* a3d = (const float*)d_in[12];
    const float* b3 = (const float*)d_in[13];
    float* out = (float*)d_out;

    int N = in_sizes[0] / 256;
    int E = in_sizes[1] / 2;
    int nb = (N + 255) / 256;

    // One-time side stream + events (created on the correctness call, which
    // is NOT captured; reused identically on every call thereafter).
    static cudaStream_t s_side = nullptr;
    static cudaEvent_t ev_fork = nullptr, ev_join = nullptr;
    if (!s_side) {
        cudaStreamCreateWithFlags(&s_side, cudaStreamNonBlocking);
        cudaEventCreateWithFlags(&ev_fork, cudaEventDisableTiming);
        cudaEventCreateWithFlags(&ev_join, cudaEventDisableTiming);
    }

    constexpr int SMEM1 = (2 * 128 * 36 + 2 * 32 * (128 + 8) + 2 * 128) * 4;
    constexpr int SMEM2 = (2 * 128 * 36 + 2 * 32 * (64 + 8) + 2 * 64) * 4;
    cudaFuncSetAttribute((const void*)gemm_mma_kernel<256, 128, 8, 16, false>,
                         cudaFuncAttributeMaxDynamicSharedMemorySize, SMEM1);
    cudaFuncSetAttribute((const void*)gemm_mma_kernel<128, 64, 8, 8, true>,
                         cudaFuncAttributeMaxDynamicSharedMemorySize, SMEM2);

    // Fork: CSR build on side stream, GEMM1 on main stream.
    cudaEventRecord(ev_fork, 0);
    cudaStreamWaitEvent(s_side, ev_fork, 0);

    detect_kernel<<<1, 1, 0, s_side>>>(ei, N);
    init_deg_kernel<<<(N + 255) / 256, 256, 0, s_side>>>(N);
    convert_hist_kernel<<<(E + 255) / 256, 256, 0, s_side>>>(ei, E);
    scan_blocks_kernel<<<nb, 256, 0, s_side>>>(N);
    scan_top_kernel<<<1, 1024, 0, s_side>>>(nb, N);
    scan_add_seed_kernel<<<nb, 256, 0, s_side>>>(N);
    scatter_kernel<<<(E + 255) / 256, 256, 0, s_side>>>(E);
    cudaEventRecord(ev_join, s_side);

    int warp_blocks = (N + 7) / 8;
    int gemm_blocks = (N + 127) / 128;

    // --- Layer 1 GEMM (overlaps CSR build) ---
    gemm_mma_kernel<256, 128, 8, 16, false><<<gemm_blocks, 256, SMEM1>>>(x, W1, a1s, a1d, N);

    // Join: aggregation needs both CSR and GEMM1.
    cudaStreamWaitEvent(0, ev_join, 0);

    aggregate_kernel<8, 16, true><<<warp_blocks, 256>>>(b1, N);

    // --- Layer 2 ---
    gemm_mma_kernel<128, 64, 8, 8, true><<<gemm_blocks, 256, SMEM2>>>(nullptr, W2, a2s, a2d, N);
    aggregate_kernel<8, 8, true><<<warp_blocks, 256>>>(b2, N);

    // --- Layer 3 ---
    gemm3_kernel<<<warp_blocks, 256>>>(W3, a3s, a3d, N);
    aggregate3_kernel<<<(N + 255) / 256, 256>>>(b3, out, N);
}

// round 6
// speedup vs baseline: 2.8366x; 1.0003x over previous
#include <cuda_runtime.h>
#include <cuda_fp16.h>
#include <math.h>
#include <stdint.h>

// ---------------------------------------------------------------------------
// N=100000 nodes, F=256, E=1600000.
// Layer 1: 256 -> 8 heads x 16   (HC=128)
// Layer 2: 128 -> 8 heads x 8    (HC=64)
// Layer 3:  64 -> 1 head  x 10   (HC=10), then log_softmax
// ---------------------------------------------------------------------------
#define MAXN 100000
#define MAXE 1600000

__device__ __align__(16) __half g_xp[MAXN * 128];  // transformed features (fp16, gathered)
__device__ __align__(16) float g_h [MAXN * 128];   // layer activations (fp32)
__device__ __align__(16) float g_xp3[MAXN * 16];   // layer-3 logits (fp32)
__device__ float g_asrc[MAXN * 8];
__device__ float g_adst[MAXN * 8];
__device__ int   g_srcbuf[MAXE];
__device__ int   g_dstbuf[MAXE];
__device__ int   g_deg[MAXN];
__device__ int   g_cursor[MAXN];
__device__ int   g_row[MAXN + 1];
__device__ int   g_csr[MAXE + MAXN];
__device__ int   g_bsum[1024];
__device__ int   g_boff[1024];
__device__ int   g_is64;

// ---------------------------------------------------------------------------
// PTX helpers
// ---------------------------------------------------------------------------
__device__ __forceinline__ void cp_async16(uint32_t dst, const void* src) {
    asm volatile("cp.async.cg.shared.global [%0], [%1], 16;" :: "r"(dst), "l"(src));
}
#define CP_COMMIT() asm volatile("cp.async.commit_group;")
#define CP_WAIT0()  asm volatile("cp.async.wait_group 0;")

__device__ __forceinline__ uint32_t f2tf(float f) {
    uint32_t r;
    asm("cvt.rna.tf32.f32 %0, %1;" : "=r"(r) : "f"(f));
    return r;
}

__device__ __forceinline__ void mma_tf32(float& d0, float& d1, float& d2, float& d3,
                                         uint32_t a0, uint32_t a1, uint32_t a2, uint32_t a3,
                                         uint32_t b0, uint32_t b1) {
    asm("mma.sync.aligned.m16n8k8.row.col.f32.tf32.tf32.f32 "
        "{%0,%1,%2,%3}, {%4,%5,%6,%7}, {%8,%9}, {%0,%1,%2,%3};"
        : "+f"(d0), "+f"(d1), "+f"(d2), "+f"(d3)
        : "r"(a0), "r"(a1), "r"(a2), "r"(a3), "r"(b0), "r"(b1));
}

// ---------------------------------------------------------------------------
// Edge dtype detection + conversion + degree histogram
// ---------------------------------------------------------------------------
__global__ void detect_kernel(const void* ei, int N) {
    const long long* p = (const long long*)ei;
    int ok = 1;
    for (int i = 0; i < 8; i++) {
        long long v = p[i];
        if (v < 0 || v >= (long long)N) ok = 0;
    }
    g_is64 = ok;
}

__global__ void init_deg_kernel(int N) {
    int i = blockIdx.x * blockDim.x + threadIdx.x;
    if (i < N) g_deg[i] = 1;   // self loop
}

__global__ void convert_hist_kernel(const void* ei, int E) {
    int e = blockIdx.x * blockDim.x + threadIdx.x;
    if (e >= E) return;
    int src, dst;
    if (g_is64) {
        const long long* p = (const long long*)ei;
        src = (int)p[e];
        dst = (int)p[(size_t)E + e];
    } else {
        const int* p = (const int*)ei;
        src = p[e];
        dst = p[(size_t)E + e];
    }
    g_srcbuf[e] = src;
    g_dstbuf[e] = dst;
    atomicAdd(&g_deg[dst], 1);
}

// ---------------------------------------------------------------------------
// Parallel exclusive scan (3 kernels), seed self loops + cursors
// ---------------------------------------------------------------------------
__global__ void scan_blocks_kernel(int N) {
    int i = blockIdx.x * 256 + threadIdx.x;
    int v = (i < N) ? g_deg[i] : 0;
    int lane = threadIdx.x & 31, wid = threadIdx.x >> 5;
    int x = v;
#pragma unroll
    for (int off = 1; off < 32; off <<= 1) {
        int t = __shfl_up_sync(0xFFFFFFFFu, x, off);
        if (lane >= off) x += t;
    }
    __shared__ int wsum[8];
    if (lane == 31) wsum[wid] = x;
    __syncthreads();
    if (threadIdx.x == 0) {
        int run = 0;
#pragma unroll
        for (int w = 0; w < 8; w++) { int t = wsum[w]; wsum[w] = run; run += t; }
        g_bsum[blockIdx.x] = run;
    }
    __syncthreads();
    if (i < N) g_row[i] = x - v + wsum[wid];
}

__global__ void scan_top_kernel(int nb, int N) {
    int t = threadIdx.x;
    int v = (t < nb) ? g_bsum[t] : 0;
    int lane = t & 31, wid = t >> 5;
    int x = v;
#pragma unroll
    for (int off = 1; off < 32; off <<= 1) {
        int s = __shfl_up_sync(0xFFFFFFFFu, x, off);
        if (lane >= off) x += s;
    }
    __shared__ int wsum[32];
    if (lane == 31) wsum[wid] = x;
    __syncthreads();
    if (t == 0) {
        int run = 0;
#pragma unroll
        for (int w = 0; w < 32; w++) { int s = wsum[w]; wsum[w] = run; run += s; }
        g_row[N] = run;
    }
    __syncthreads();
    if (t < nb) g_boff[t] = x - v + wsum[wid];
}

__global__ void scan_add_seed_kernel(int N) {
    int i = blockIdx.x * 256 + threadIdx.x;
    if (i >= N) return;
    int r = g_row[i] + g_boff[i >> 8];
    g_row[i] = r;
    g_csr[r] = i;          // self loop in slot 0
    g_cursor[i] = r + 1;
}

__global__ void scatter_kernel(int E) {
    int e = blockIdx.x * blockDim.x + threadIdx.x;
    if (e < E) {
        int pos = atomicAdd(&g_cursor[g_dstbuf[e]], 1);
        g_csr[pos] = g_srcbuf[e];
    }
}

// ---------------------------------------------------------------------------
// Tensor-core GEMM (tf32 mma.sync) + fused attention logits.
// xp (fp16) = A[N,KIN] @ W[KIN,KOUT]; asrc/adst from fp32 accumulators.
// BM=128, BN=KOUT, BK=32, 8 warps in 4(M) x 2(N); warp tile 32 x (BN/2).
// ---------------------------------------------------------------------------
template <int KIN, int KOUT, int H, int C, bool READ_H>
__global__ void gemm_mma_kernel(const float* __restrict__ Ain,
                                const float* __restrict__ W,
                                const float* __restrict__ a_s,
                                const float* __restrict__ a_d,
                                int N) {
    constexpr int BM = 128, BK = 32, BN = KOUT;
    constexpr int NT = 256;
    constexpr int SA = 36;             // A smem row stride (floats)
    constexpr int SB = BN + 8;         // B smem row stride (floats)
    constexpr int T  = KIN / BK;
    constexpr int BNW = BN / 2;        // warp N-span
    constexpr int NTILES = BNW / 8;
    constexpr int MTILES = 2;
    constexpr int NHL = BNW / C;       // heads per warp
    constexpr int AS_SZ = 2 * BM * SA;
    constexpr int BS_SZ = 2 * BK * SB;

    extern __shared__ float sm[];
    float* As  = sm;
    float* Bs  = sm + AS_SZ;
    float* s_as = sm + AS_SZ + BS_SZ;
    float* s_ad = s_as + BN;

    const float* A = READ_H ? g_h : Ain;
    int tid = threadIdx.x;
    int row0 = blockIdx.x * BM;

    for (int i = tid; i < BN; i += NT) { s_as[i] = a_s[i]; s_ad[i] = a_d[i]; }

    auto load_tile = [&](int t, int b) {
        int k0 = t * BK;
#pragma unroll
        for (int idx = tid; idx < BM * (BK / 4); idx += NT) {
            int m = idx >> 3, k4 = idx & 7;
            int gr = min(row0 + m, N - 1);
            cp_async16((uint32_t)__cvta_generic_to_shared(&As[b * BM * SA + m * SA + k4 * 4]),
                       &A[(size_t)gr * KIN + k0 + k4 * 4]);
        }
#pragma unroll
        for (int idx = tid; idx < BK * (BN / 4); idx += NT) {
            int k = idx / (BN / 4), n4 = idx % (BN / 4);
            cp_async16((uint32_t)__cvta_generic_to_shared(&Bs[b * BK * SB + k * SB + n4 * 4]),
                       &W[(size_t)(k0 + k) * KOUT + n4 * 4]);
        }
        CP_COMMIT();
    };

    int lane = tid & 31;
    int gid = lane >> 2, tig = lane & 3;
    int w = tid >> 5;
    int warp_n = w & 1, warp_m = w >> 1;
    int mbase = warp_m * 32;
    int nbase = warp_n * BNW;

    float acc[MTILES][NTILES][4];
#pragma unroll
    for (int mt = 0; mt < MTILES; mt++)
#pragma unroll
        for (int nt = 0; nt < NTILES; nt++)
#pragma unroll
            for (int q = 0; q < 4; q++) acc[mt][nt][q] = 0.f;

    load_tile(0, 0);
    CP_WAIT0();
    __syncthreads();

    for (int t = 0; t < T; t++) {
        if (t + 1 < T) load_tile(t + 1, (t + 1) & 1);
        int b = t & 1;
        const float* Ab = &As[b * BM * SA];
        const float* Bb = &Bs[b * BK * SB];
#pragma unroll
        for (int k8 = 0; k8 < BK / 8; k8++) {
            int kk = k8 * 8;
            uint32_t af[MTILES][4];
#pragma unroll
            for (int mt = 0; mt < MTILES; mt++) {
                const float* ar = &Ab[(mbase + mt * 16 + gid) * SA + kk + tig];
                af[mt][0] = f2tf(ar[0]);
                af[mt][1] = f2tf(ar[8 * SA]);
                af[mt][2] = f2tf(ar[4]);
                af[mt][3] = f2tf(ar[8 * SA + 4]);
            }
            uint32_t bf[NTILES][2];
#pragma unroll
            for (int nt = 0; nt < NTILES; nt++) {
                const float* br = &Bb[(kk + tig) * SB + nbase + nt * 8 + gid];
                bf[nt][0] = f2tf(br[0]);
                bf[nt][1] = f2tf(br[4 * SB]);
            }
#pragma unroll
            for (int mt = 0; mt < MTILES; mt++)
#pragma unroll
                for (int nt = 0; nt < NTILES; nt++)
                    mma_tf32(acc[mt][nt][0], acc[mt][nt][1], acc[mt][nt][2], acc[mt][nt][3],
                             af[mt][0], af[mt][1], af[mt][2], af[mt][3],
                             bf[nt][0], bf[nt][1]);
        }
        if (t + 1 < T) {
            CP_WAIT0();
            __syncthreads();
        }
    }

    // Epilogue: store xp (fp16), fused attention logits from fp32 accumulators
#pragma unroll
    for (int mt = 0; mt < MTILES; mt++) {
        int r0 = row0 + mbase + mt * 16 + gid;
        int r1 = r0 + 8;
        float ps0[NHL], pd0[NHL], ps1[NHL], pd1[NHL];
#pragma unroll
        for (int hl = 0; hl < NHL; hl++) { ps0[hl] = pd0[hl] = ps1[hl] = pd1[hl] = 0.f; }
#pragma unroll
        for (int nt = 0; nt < NTILES; nt++) {
            int col = nbase + nt * 8 + 2 * tig;
            int hl = (nt * 8) / C;
            float d0 = acc[mt][nt][0], d1 = acc[mt][nt][1];
            float d2 = acc[mt][nt][2], d3 = acc[mt][nt][3];
            if (r0 < N) *reinterpret_cast<__half2*>(&g_xp[(size_t)r0 * KOUT + col]) =
                __floats2half2_rn(d0, d1);
            if (r1 < N) *reinterpret_cast<__half2*>(&g_xp[(size_t)r1 * KOUT + col]) =
                __floats2half2_rn(d2, d3);
            float w0 = s_as[col], w1 = s_as[col + 1];
            float v0 = s_ad[col], v1 = s_ad[col + 1];
            ps0[hl] += d0 * w0 + d1 * w1;
            pd0[hl] += d0 * v0 + d1 * v1;
            ps1[hl] += d2 * w0 + d3 * w1;
            pd1[hl] += d2 * v0 + d3 * v1;
        }
#pragma unroll
        for (int hl = 0; hl < NHL; hl++) {
            ps0[hl] += __shfl_xor_sync(0xFFFFFFFFu, ps0[hl], 1);
            ps0[hl] += __shfl_xor_sync(0xFFFFFFFFu, ps0[hl], 2);
            pd0[hl] += __shfl_xor_sync(0xFFFFFFFFu, pd0[hl], 1);
            pd0[hl] += __shfl_xor_sync(0xFFFFFFFFu, pd0[hl], 2);
            ps1[hl] += __shfl_xor_sync(0xFFFFFFFFu, ps1[hl], 1);
            ps1[hl] += __shfl_xor_sync(0xFFFFFFFFu, ps1[hl], 2);
            pd1[hl] += __shfl_xor_sync(0xFFFFFFFFu, pd1[hl], 1);
            pd1[hl] += __shfl_xor_sync(0xFFFFFFFFu, pd1[hl], 2);
        }
        if (tig == 0) {
#pragma unroll
            for (int hl = 0; hl < NHL; hl++) {
                int head = nbase / C + hl;
                if (r0 < N) {
                    g_asrc[(size_t)r0 * H + head] = ps0[hl];
                    g_adst[(size_t)r0 * H + head] = pd0[hl];
                }
                if (r1 < N) {
                    g_asrc[(size_t)r1 * H + head] = ps1[hl];
                    g_adst[(size_t)r1 * H + head] = pd1[hl];
                }
            }
        }
    }
}

// ---------------------------------------------------------------------------
// Aggregation: warp-per-dst, two-pass softmax (max exact via LeakyReLU
// monotonicity), branch-free fp16 gather, fp32 accumulation.
// ---------------------------------------------------------------------------
template <int H, int C, bool DO_ELU>
__global__ void aggregate_kernel(const float* __restrict__ bias, int N) {
    constexpr int HC = H * C;
    constexpr int VPL = HC / 32;       // values per lane (4 / 2)
    constexpr int LPH = C / VPL;       // lanes per head
    int d = (blockIdx.x * blockDim.x + threadIdx.x) >> 5;
    int lane = threadIdx.x & 31;
    if (d >= N) return;
    int head = lane / LPH;
    int sub  = lane % LPH;
    float adst_h = g_adst[(size_t)d * H + head];

    int lo = g_row[d], hi = g_row[d + 1];

    float ma = -INFINITY;
    for (int i = lo + sub; i < hi; i += LPH)
        ma = fmaxf(ma, g_asrc[(size_t)g_csr[i] * H + head]);
#pragma unroll
    for (int off = LPH / 2; off >= 1; off >>= 1)
        ma = fmaxf(ma, __shfl_xor_sync(0xFFFFFFFFu, ma, off));
    float em = ma + adst_h;
    float m = (em > 0.f) ? em : 0.2f * em;

    float s = 0.f;
    float acc[VPL];
#pragma unroll
    for (int v = 0; v < VPL; v++) acc[v] = 0.f;

#pragma unroll 4
    for (int i = lo; i < hi; i++) {
        int src = g_csr[i];
        float e = g_asrc[(size_t)src * H + head] + adst_h;
        e = (e > 0.f) ? e : 0.2f * e;
        float wgt = __expf(e - m);
        s += wgt;
        const __half* row = g_xp + (size_t)src * HC + lane * VPL;
        if constexpr (VPL == 4) {
            uint2 raw = *reinterpret_cast<const uint2*>(row);
            float2 fa = __half22float2(*reinterpret_cast<__half2*>(&raw.x));
            float2 fb = __half22float2(*reinterpret_cast<__half2*>(&raw.y));
            acc[0] += wgt * fa.x; acc[1] += wgt * fa.y;
            acc[2] += wgt * fb.x; acc[3] += wgt * fb.y;
        } else {
            float2 fa = __half22float2(*reinterpret_cast<const __half2*>(row));
            acc[0] += wgt * fa.x; acc[1] += wgt * fa.y;
        }
    }
    float inv = 1.f / (s + 1e-16f);
#pragma unroll
    for (int v = 0; v < VPL; v++) {
        float o = acc[v] * inv + bias[lane * VPL + v];
        if (DO_ELU) o = (o > 0.f) ? o : expm1f(o);
        g_h[(size_t)d * HC + lane * VPL + v] = o;
    }
}

// ---------------------------------------------------------------------------
// Layer 3 GEMM: xp3[N,10] = h[N,64] @ W3[64,10] (stride 16) + attn logits.
// ---------------------------------------------------------------------------
__global__ void gemm3_kernel(const float* __restrict__ W3,
                             const float* __restrict__ a_s, const float* __restrict__ a_d,
                             int N) {
    __shared__ float Ws[64 * 10];
    __shared__ float as_s[10], ad_s[10];
    int t = threadIdx.x;
    for (int i = t; i < 640; i += blockDim.x) Ws[i] = W3[i];
    if (t < 10) { as_s[t] = a_s[t]; ad_s[t] = a_d[t]; }
    __syncthreads();

    int r = (blockIdx.x * blockDim.x + t) >> 5;
    int lane = t & 31;
    if (r >= N) return;
    float h0 = g_h[(size_t)r * 64 + lane];
    float h1 = g_h[(size_t)r * 64 + 32 + lane];
    float p[10];
#pragma unroll
    for (int c = 0; c < 10; c++)
        p[c] = h0 * Ws[lane * 10 + c] + h1 * Ws[(lane + 32) * 10 + c];
#pragma unroll
    for (int c = 0; c < 10; c++) {
#pragma unroll
        for (int off = 16; off >= 1; off >>= 1)
            p[c] += __shfl_xor_sync(0xFFFFFFFFu, p[c], off);
    }
    if (lane == 0) {
        float ss = 0.f, sd = 0.f;
#pragma unroll
        for (int c = 0; c < 10; c++) {
            g_xp3[(size_t)r * 16 + c] = p[c];
            ss += p[c] * as_s[c];
            sd += p[c] * ad_s[c];
        }
        g_asrc[r] = ss;
        g_adst[r] = sd;
    }
}

// ---------------------------------------------------------------------------
// Layer 3 aggregation + log_softmax. One thread per destination, two-pass.
// ---------------------------------------------------------------------------
__global__ void aggregate3_kernel(const float* __restrict__ bias,
                                  float* __restrict__ out, int N) {
    int d = blockIdx.x * blockDim.x + threadIdx.x;
    if (d >= N) return;
    float adst_d = g_adst[d];
    int lo = g_row[d], hi = g_row[d + 1];

    float ma = -INFINITY;
    for (int i = lo; i < hi; i++)
        ma = fmaxf(ma, g_asrc[g_csr[i]]);
    float em = ma + adst_d;
    float m = (em > 0.f) ? em : 0.2f * em;

    float s = 0.f;
    float acc[10];
#pragma unroll
    for (int c = 0; c < 10; c++) acc[c] = 0.f;

    for (int i = lo; i < hi; i++) {
        int src = g_csr[i];
        float e = g_asrc[src] + adst_d;
        e = (e > 0.f) ? e : 0.2f * e;
        float wgt = __expf(e - m);
        s += wgt;
        const float* row = g_xp3 + (size_t)src * 16;
        float4 v0 = *reinterpret_cast<const float4*>(row);
        float4 v1 = *reinterpret_cast<const float4*>(row + 4);
        float2 v2 = *reinterpret_cast<const float2*>(row + 8);
        acc[0] += wgt * v0.x; acc[1] += wgt * v0.y; acc[2] += wgt * v0.z; acc[3] += wgt * v0.w;
        acc[4] += wgt * v1.x; acc[5] += wgt * v1.y; acc[6] += wgt * v1.z; acc[7] += wgt * v1.w;
        acc[8] += wgt * v2.x; acc[9] += wgt * v2.y;
    }
    float inv = 1.f / (s + 1e-16f);
    float logit[10];
    float mx = -INFINITY;
#pragma unroll
    for (int c = 0; c < 10; c++) {
        logit[c] = acc[c] * inv + bias[c];
        mx = fmaxf(mx, logit[c]);
    }
    float se = 0.f;
#pragma unroll
    for (int c = 0; c < 10; c++) se += __expf(logit[c] - mx);
    float lse = logf(se) + mx;
#pragma unroll
    for (int c = 0; c < 10; c++) out[(size_t)d * 10 + c] = logit[c] - lse;
}

// ---------------------------------------------------------------------------
// Launcher (CSR build forked onto a side stream, overlapped with GEMM1)
// ---------------------------------------------------------------------------
extern "C" void kernel_launch(void* const* d_in, const int* in_sizes, int n_in,
                              void* d_out, int out_size) {
    const float* x   = (const float*)d_in[0];
    const void*  ei  = d_in[1];
    const float* W1 = (const float*)d_in[2];
    const float* a1s = (const float*)d_in[3];
    const float* a1d = (const float*)d_in[4];
    const float* b1 = (const float*)d_in[5];
    const float* W2 = (const float*)d_in[6];
    const float* a2s = (const float*)d_in[7];
    const float* a2d = (const float*)d_in[8];
    const float* b2 = (const float*)d_in[9];
    const float* W3 = (const float*)d_in[10];
    const float* a3s = (const float*)d_in[11];
    const float* a3d = (const float*)d_in[12];
    const float* b3 = (const float*)d_in[13];
    float* out = (float*)d_out;

    int N = in_sizes[0] / 256;
    int E = in_sizes[1] / 2;
    int nb = (N + 255) / 256;

    static cudaStream_t s_side = nullptr;
    static cudaEvent_t ev_fork = nullptr, ev_join = nullptr;
    if (!s_side) {
        cudaStreamCreateWithFlags(&s_side, cudaStreamNonBlocking);
        cudaEventCreateWithFlags(&ev_fork, cudaEventDisableTiming);
        cudaEventCreateWithFlags(&ev_join, cudaEventDisableTiming);
    }

    constexpr int SMEM1 = (2 * 128 * 36 + 2 * 32 * (128 + 8) + 2 * 128) * 4;
    constexpr int SMEM2 = (2 * 128 * 36 + 2 * 32 * (64 + 8) + 2 * 64) * 4;
    cudaFuncSetAttribute((const void*)gemm_mma_kernel<256, 128, 8, 16, false>,
                         cudaFuncAttributeMaxDynamicSharedMemorySize, SMEM1);
    cudaFuncSetAttribute((const void*)gemm_mma_kernel<128, 64, 8, 8, true>,
                         cudaFuncAttributeMaxDynamicSharedMemorySize, SMEM2);

    // Fork: CSR build on side stream, GEMM1 on main stream.
    cudaEventRecord(ev_fork, 0);
    cudaStreamWaitEvent(s_side, ev_fork, 0);

    detect_kernel<<<1, 1, 0, s_side>>>(ei, N);
    init_deg_kernel<<<(N + 255) / 256, 256, 0, s_side>>>(N);
    convert_hist_kernel<<<(E + 255) / 256, 256, 0, s_side>>>(ei, E);
    scan_blocks_kernel<<<nb, 256, 0, s_side>>>(N);
    scan_top_kernel<<<1, 1024, 0, s_side>>>(nb, N);
    scan_add_seed_kernel<<<nb, 256, 0, s_side>>>(N);
    scatter_kernel<<<(E + 255) / 256, 256, 0, s_side>>>(E);
    cudaEventRecord(ev_join, s_side);

    int warp_blocks = (N + 7) / 8;
    int gemm_blocks = (N + 127) / 128;

    // --- Layer 1 GEMM (overlaps CSR build) ---
    gemm_mma_kernel<256, 128, 8, 16, false><<<gemm_blocks, 256, SMEM1>>>(x, W1, a1s, a1d, N);

    cudaStreamWaitEvent(0, ev_join, 0);

    aggregate_kernel<8, 16, true><<<warp_blocks, 256>>>(b1, N);

    // --- Layer 2 ---
    gemm_mma_kernel<128, 64, 8, 8, true><<<gemm_blocks, 256, SMEM2>>>(nullptr, W2, a2s, a2d, N);
    aggregate_kernel<8, 8, true><<<warp_blocks, 256>>>(b2, N);

    // --- Layer 3 ---
    gemm3_kernel<<<warp_blocks, 256>>>(W3, a3s, a3d, N);
    aggregate3_kernel<<<(N + 255) / 256, 256>>>(b3, out, N);
}

// round 7
// speedup vs baseline: 2.8467x; 1.0036x over previous
#include <cuda_runtime.h>
#include <cuda_fp16.h>
#include <math.h>
#include <stdint.h>

// ---------------------------------------------------------------------------
// N=100000 nodes, F=256, E=1600000.
// Layer 1: 256 -> 8 heads x 16   (HC=128)
// Layer 2: 128 -> 8 heads x 8    (HC=64)
// Layer 3:  64 -> 1 head  x 10   (HC=10), then log_softmax
// ---------------------------------------------------------------------------
#define MAXN 100000
#define MAXE 1600000

__device__ __align__(16) __half g_xp[MAXN * 128];  // transformed features (fp16, gathered)
__device__ __align__(16) float g_h [MAXN * 128];   // layer activations (fp32)
__device__ __align__(16) float g_xp3[MAXN * 16];   // layer-3 logits (fp32)
__device__ float g_asrc[MAXN * 8];
__device__ float g_adst[MAXN * 8];
__device__ int   g_srcbuf[MAXE];
__device__ int   g_dstbuf[MAXE];
__device__ int   g_deg[MAXN];
__device__ int   g_cursor[MAXN];
__device__ int   g_row[MAXN + 1];
__device__ int   g_csr[MAXE + MAXN];
__device__ int   g_bsum[1024];
__device__ int   g_boff[1024];

// ---------------------------------------------------------------------------
// PTX helpers
// ---------------------------------------------------------------------------
__device__ __forceinline__ void cp_async16(uint32_t dst, const void* src) {
    asm volatile("cp.async.cg.shared.global [%0], [%1], 16;" :: "r"(dst), "l"(src));
}
#define CP_COMMIT() asm volatile("cp.async.commit_group;")
#define CP_WAIT0()  asm volatile("cp.async.wait_group 0;")

__device__ __forceinline__ uint32_t f2tf(float f) {
    uint32_t r;
    asm("cvt.rna.tf32.f32 %0, %1;" : "=r"(r) : "f"(f));
    return r;
}

__device__ __forceinline__ void mma_tf32(float& d0, float& d1, float& d2, float& d3,
                                         uint32_t a0, uint32_t a1, uint32_t a2, uint32_t a3,
                                         uint32_t b0, uint32_t b1) {
    asm("mma.sync.aligned.m16n8k8.row.col.f32.tf32.tf32.f32 "
        "{%0,%1,%2,%3}, {%4,%5,%6,%7}, {%8,%9}, {%0,%1,%2,%3};"
        : "+f"(d0), "+f"(d1), "+f"(d2), "+f"(d3)
        : "r"(a0), "r"(a1), "r"(a2), "r"(a3), "r"(b0), "r"(b1));
}

// ---------------------------------------------------------------------------
// Edge conversion (dtype detect inlined) + degree histogram
// ---------------------------------------------------------------------------
__global__ void convert_hist_kernel(const void* ei, int E, int N) {
    __shared__ int s64;
    if (threadIdx.x == 0) {
        const long long* p = (const long long*)ei;
        int ok = 1;
        for (int i = 0; i < 8; i++) {
            long long v = p[i];
            if (v < 0 || v >= (long long)N) ok = 0;
        }
        s64 = ok;
    }
    __syncthreads();
    int e = blockIdx.x * blockDim.x + threadIdx.x;
    if (e >= E) return;
    int src, dst;
    if (s64) {
        const long long* p = (const long long*)ei;
        src = (int)p[e];
        dst = (int)p[(size_t)E + e];
    } else {
        const int* p = (const int*)ei;
        src = p[e];
        dst = p[(size_t)E + e];
    }
    g_srcbuf[e] = src;
    g_dstbuf[e] = dst;
    atomicAdd(&g_deg[dst], 1);
}

// ---------------------------------------------------------------------------
// Parallel exclusive scan (3 kernels) over (deg+1), seed self loops + cursors
// ---------------------------------------------------------------------------
__global__ void scan_blocks_kernel(int N) {
    int i = blockIdx.x * 256 + threadIdx.x;
    int v = (i < N) ? g_deg[i] + 1 : 0;   // +1 = self loop
    int lane = threadIdx.x & 31, wid = threadIdx.x >> 5;
    int x = v;
#pragma unroll
    for (int off = 1; off < 32; off <<= 1) {
        int t = __shfl_up_sync(0xFFFFFFFFu, x, off);
        if (lane >= off) x += t;
    }
    __shared__ int wsum[8];
    if (lane == 31) wsum[wid] = x;
    __syncthreads();
    if (threadIdx.x == 0) {
        int run = 0;
#pragma unroll
        for (int w = 0; w < 8; w++) { int t = wsum[w]; wsum[w] = run; run += t; }
        g_bsum[blockIdx.x] = run;
    }
    __syncthreads();
    if (i < N) g_row[i] = x - v + wsum[wid];
}

__global__ void scan_top_kernel(int nb, int N) {
    int t = threadIdx.x;
    int v = (t < nb) ? g_bsum[t] : 0;
    int lane = t & 31, wid = t >> 5;
    int x = v;
#pragma unroll
    for (int off = 1; off < 32; off <<= 1) {
        int s = __shfl_up_sync(0xFFFFFFFFu, x, off);
        if (lane >= off) x += s;
    }
    __shared__ int wsum[32];
    if (lane == 31) wsum[wid] = x;
    __syncthreads();
    if (t == 0) {
        int run = 0;
#pragma unroll
        for (int w = 0; w < 32; w++) { int s = wsum[w]; wsum[w] = run; run += s; }
        g_row[N] = run;
    }
    __syncthreads();
    if (t < nb) g_boff[t] = x - v + wsum[wid];
}

__global__ void scan_add_seed_kernel(int N) {
    int i = blockIdx.x * 256 + threadIdx.x;
    if (i >= N) return;
    int r = g_row[i] + g_boff[i >> 8];
    g_row[i] = r;
    g_csr[r] = i;          // self loop in slot 0
    g_cursor[i] = r + 1;
}

__global__ void scatter_kernel(int E) {
    int e = blockIdx.x * blockDim.x + threadIdx.x;
    if (e < E) {
        int pos = atomicAdd(&g_cursor[g_dstbuf[e]], 1);
        g_csr[pos] = g_srcbuf[e];
    }
}

// ---------------------------------------------------------------------------
// Tensor-core GEMM (tf32 mma.sync) + fused attention logits.
// xp (fp16) = A[N,KIN] @ W[KIN,KOUT]; asrc/adst from fp32 accumulators.
// ---------------------------------------------------------------------------
template <int KIN, int KOUT, int H, int C, bool READ_H>
__global__ void gemm_mma_kernel(const float* __restrict__ Ain,
                                const float* __restrict__ W,
                                const float* __restrict__ a_s,
                                const float* __restrict__ a_d,
                                int N) {
    constexpr int BM = 128, BK = 32, BN = KOUT;
    constexpr int NT = 256;
    constexpr int SA = 36;
    constexpr int SB = BN + 8;
    constexpr int T  = KIN / BK;
    constexpr int BNW = BN / 2;
    constexpr int NTILES = BNW / 8;
    constexpr int MTILES = 2;
    constexpr int NHL = BNW / C;
    constexpr int AS_SZ = 2 * BM * SA;
    constexpr int BS_SZ = 2 * BK * SB;

    extern __shared__ float sm[];
    float* As  = sm;
    float* Bs  = sm + AS_SZ;
    float* s_as = sm + AS_SZ + BS_SZ;
    float* s_ad = s_as + BN;

    const float* A = READ_H ? g_h : Ain;
    int tid = threadIdx.x;
    int row0 = blockIdx.x * BM;

    for (int i = tid; i < BN; i += NT) { s_as[i] = a_s[i]; s_ad[i] = a_d[i]; }

    auto load_tile = [&](int t, int b) {
        int k0 = t * BK;
#pragma unroll
        for (int idx = tid; idx < BM * (BK / 4); idx += NT) {
            int m = idx >> 3, k4 = idx & 7;
            int gr = min(row0 + m, N - 1);
            cp_async16((uint32_t)__cvta_generic_to_shared(&As[b * BM * SA + m * SA + k4 * 4]),
                       &A[(size_t)gr * KIN + k0 + k4 * 4]);
        }
#pragma unroll
        for (int idx = tid; idx < BK * (BN / 4); idx += NT) {
            int k = idx / (BN / 4), n4 = idx % (BN / 4);
            cp_async16((uint32_t)__cvta_generic_to_shared(&Bs[b * BK * SB + k * SB + n4 * 4]),
                       &W[(size_t)(k0 + k) * KOUT + n4 * 4]);
        }
        CP_COMMIT();
    };

    int lane = tid & 31;
    int gid = lane >> 2, tig = lane & 3;
    int w = tid >> 5;
    int warp_n = w & 1, warp_m = w >> 1;
    int mbase = warp_m * 32;
    int nbase = warp_n * BNW;

    float acc[MTILES][NTILES][4];
#pragma unroll
    for (int mt = 0; mt < MTILES; mt++)
#pragma unroll
        for (int nt = 0; nt < NTILES; nt++)
#pragma unroll
            for (int q = 0; q < 4; q++) acc[mt][nt][q] = 0.f;

    load_tile(0, 0);
    CP_WAIT0();
    __syncthreads();

    for (int t = 0; t < T; t++) {
        if (t + 1 < T) load_tile(t + 1, (t + 1) & 1);
        int b = t & 1;
        const float* Ab = &As[b * BM * SA];
        const float* Bb = &Bs[b * BK * SB];
#pragma unroll
        for (int k8 = 0; k8 < BK / 8; k8++) {
            int kk = k8 * 8;
            uint32_t af[MTILES][4];
#pragma unroll
            for (int mt = 0; mt < MTILES; mt++) {
                const float* ar = &Ab[(mbase + mt * 16 + gid) * SA + kk + tig];
                af[mt][0] = f2tf(ar[0]);
                af[mt][1] = f2tf(ar[8 * SA]);
                af[mt][2] = f2tf(ar[4]);
                af[mt][3] = f2tf(ar[8 * SA + 4]);
            }
            uint32_t bf[NTILES][2];
#pragma unroll
            for (int nt = 0; nt < NTILES; nt++) {
                const float* br = &Bb[(kk + tig) * SB + nbase + nt * 8 + gid];
                bf[nt][0] = f2tf(br[0]);
                bf[nt][1] = f2tf(br[4 * SB]);
            }
#pragma unroll
            for (int mt = 0; mt < MTILES; mt++)
#pragma unroll
                for (int nt = 0; nt < NTILES; nt++)
                    mma_tf32(acc[mt][nt][0], acc[mt][nt][1], acc[mt][nt][2], acc[mt][nt][3],
                             af[mt][0], af[mt][1], af[mt][2], af[mt][3],
                             bf[nt][0], bf[nt][1]);
        }
        if (t + 1 < T) {
            CP_WAIT0();
            __syncthreads();
        }
    }

#pragma unroll
    for (int mt = 0; mt < MTILES; mt++) {
        int r0 = row0 + mbase + mt * 16 + gid;
        int r1 = r0 + 8;
        float ps0[NHL], pd0[NHL], ps1[NHL], pd1[NHL];
#pragma unroll
        for (int hl = 0; hl < NHL; hl++) { ps0[hl] = pd0[hl] = ps1[hl] = pd1[hl] = 0.f; }
#pragma unroll
        for (int nt = 0; nt < NTILES; nt++) {
            int col = nbase + nt * 8 + 2 * tig;
            int hl = (nt * 8) / C;
            float d0 = acc[mt][nt][0], d1 = acc[mt][nt][1];
            float d2 = acc[mt][nt][2], d3 = acc[mt][nt][3];
            if (r0 < N) *reinterpret_cast<__half2*>(&g_xp[(size_t)r0 * KOUT + col]) =
                __floats2half2_rn(d0, d1);
            if (r1 < N) *reinterpret_cast<__half2*>(&g_xp[(size_t)r1 * KOUT + col]) =
                __floats2half2_rn(d2, d3);
            float w0 = s_as[col], w1 = s_as[col + 1];
            float v0 = s_ad[col], v1 = s_ad[col + 1];
            ps0[hl] += d0 * w0 + d1 * w1;
            pd0[hl] += d0 * v0 + d1 * v1;
            ps1[hl] += d2 * w0 + d3 * w1;
            pd1[hl] += d2 * v0 + d3 * v1;
        }
#pragma unroll
        for (int hl = 0; hl < NHL; hl++) {
            ps0[hl] += __shfl_xor_sync(0xFFFFFFFFu, ps0[hl], 1);
            ps0[hl] += __shfl_xor_sync(0xFFFFFFFFu, ps0[hl], 2);
            pd0[hl] += __shfl_xor_sync(0xFFFFFFFFu, pd0[hl], 1);
            pd0[hl] += __shfl_xor_sync(0xFFFFFFFFu, pd0[hl], 2);
            ps1[hl] += __shfl_xor_sync(0xFFFFFFFFu, ps1[hl], 1);
            ps1[hl] += __shfl_xor_sync(0xFFFFFFFFu, ps1[hl], 2);
            pd1[hl] += __shfl_xor_sync(0xFFFFFFFFu, pd1[hl], 1);
            pd1[hl] += __shfl_xor_sync(0xFFFFFFFFu, pd1[hl], 2);
        }
        if (tig == 0) {
#pragma unroll
            for (int hl = 0; hl < NHL; hl++) {
                int head = nbase / C + hl;
                if (r0 < N) {
                    g_asrc[(size_t)r0 * H + head] = ps0[hl];
                    g_adst[(size_t)r0 * H + head] = pd0[hl];
                }
                if (r1 < N) {
                    g_asrc[(size_t)r1 * H + head] = ps1[hl];
                    g_adst[(size_t)r1 * H + head] = pd1[hl];
                }
            }
        }
    }
}

// ---------------------------------------------------------------------------
// Aggregation v3: warp-per-dst, two-pass softmax with SMEM logit cache.
// Pass 1 computes e(edge, head) once (gathered asrc), caches e + src in smem,
// tracks per-head max. Pass 2 is LDS + exp + ONE gather LDG per edge.
// Edges beyond CAP (rare: deg ~ Poisson(16)) fall back to the gmem path.
// ---------------------------------------------------------------------------
template <int H, int C, bool DO_ELU>
__global__ void aggregate_kernel(const float* __restrict__ bias, int N) {
    constexpr int HC = H * C;
    constexpr int VPL = HC / 32;       // values per lane (4 / 2)
    constexpr int LPH = C / VPL;       // lanes per head (4)
    constexpr int CAP = 64;            // cached edges per warp

    __shared__ float e_cache[8][CAP][H];   // 16 KB
    __shared__ int   s_cache[8][CAP];      // 2 KB

    int wb = threadIdx.x >> 5;
    int d = (blockIdx.x * blockDim.x + threadIdx.x) >> 5;
    int lane = threadIdx.x & 31;
    if (d >= N) return;
    int head = lane / LPH;
    int sub  = lane % LPH;
    float adst_h = g_adst[(size_t)d * H + head];

    int lo = g_row[d], hi = g_row[d + 1];
    int deg = hi - lo;
    int nc = min(deg, CAP);

    // Pass 1: compute + cache logits, track per-head max
    float ma = -INFINITY;
    for (int base = 0; base < nc; base += LPH) {
        int j = base + sub;
        if (j < nc) {
            int src = g_csr[lo + j];
            float e = g_asrc[(size_t)src * H + head] + adst_h;
            e = (e > 0.f) ? e : 0.2f * e;
            e_cache[wb][j][head] = e;
            if (head == 0) s_cache[wb][j] = src;
            ma = fmaxf(ma, e);
        }
    }
    for (int base = CAP; base < deg; base += LPH) {    // overflow: max only
        int j = base + sub;
        if (j < deg) {
            int src = g_csr[lo + j];
            float e = g_asrc[(size_t)src * H + head] + adst_h;
            e = (e > 0.f) ? e : 0.2f * e;
            ma = fmaxf(ma, e);
        }
    }
#pragma unroll
    for (int off = LPH / 2; off >= 1; off >>= 1)
        ma = fmaxf(ma, __shfl_xor_sync(0xFFFFFFFFu, ma, off));
    float m = ma;
    __syncwarp();

    // Pass 2: LDS logits + single gather LDG per edge
    float s = 0.f;
    float acc[VPL];
#pragma unroll
    for (int v = 0; v < VPL; v++) acc[v] = 0.f;

#pragma unroll 4
    for (int i = 0; i < nc; i++) {
        float e = e_cache[wb][i][head];
        int src = s_cache[wb][i];
        float wgt = __expf(e - m);
        s += wgt;
        const __half* row = g_xp + (size_t)src * HC + lane * VPL;
        if constexpr (VPL == 4) {
            uint2 raw = *reinterpret_cast<const uint2*>(row);
            float2 fa = __half22float2(*reinterpret_cast<__half2*>(&raw.x));
            float2 fb = __half22float2(*reinterpret_cast<__half2*>(&raw.y));
            acc[0] += wgt * fa.x; acc[1] += wgt * fa.y;
            acc[2] += wgt * fb.x; acc[3] += wgt * fb.y;
        } else {
            float2 fa = __half22float2(*reinterpret_cast<const __half2*>(row));
            acc[0] += wgt * fa.x; acc[1] += wgt * fa.y;
        }
    }
    for (int i = CAP; i < deg; i++) {   // overflow: gmem path
        int src = g_csr[lo + i];
        float e = g_asrc[(size_t)src * H + head] + adst_h;
        e = (e > 0.f) ? e : 0.2f * e;
        float wgt = __expf(e - m);
        s += wgt;
        const __half* row = g_xp + (size_t)src * HC + lane * VPL;
        if constexpr (VPL == 4) {
            uint2 raw = *reinterpret_cast<const uint2*>(row);
            float2 fa = __half22float2(*reinterpret_cast<__half2*>(&raw.x));
            float2 fb = __half22float2(*reinterpret_cast<__half2*>(&raw.y));
            acc[0] += wgt * fa.x; acc[1] += wgt * fa.y;
            acc[2] += wgt * fb.x; acc[3] += wgt * fb.y;
        } else {
            float2 fa = __half22float2(*reinterpret_cast<const __half2*>(row));
            acc[0] += wgt * fa.x; acc[1] += wgt * fa.y;
        }
    }

    float inv = 1.f / (s + 1e-16f);
#pragma unroll
    for (int v = 0; v < VPL; v++) {
        float o = acc[v] * inv + bias[lane * VPL + v];
        if (DO_ELU) o = (o > 0.f) ? o : expm1f(o);
        g_h[(size_t)d * HC + lane * VPL + v] = o;
    }
}

// ---------------------------------------------------------------------------
// Layer 3 GEMM: xp3[N,10] = h[N,64] @ W3[64,10] (stride 16) + attn logits.
// ---------------------------------------------------------------------------
__global__ void gemm3_kernel(const float* __restrict__ W3,
                             const float* __restrict__ a_s, const float* __restrict__ a_d,
                             int N) {
    __shared__ float Ws[64 * 10];
    __shared__ float as_s[10], ad_s[10];
    int t = threadIdx.x;
    for (int i = t; i < 640; i += blockDim.x) Ws[i] = W3[i];
    if (t < 10) { as_s[t] = a_s[t]; ad_s[t] = a_d[t]; }
    __syncthreads();

    int r = (blockIdx.x * blockDim.x + t) >> 5;
    int lane = t & 31;
    if (r >= N) return;
    float h0 = g_h[(size_t)r * 64 + lane];
    float h1 = g_h[(size_t)r * 64 + 32 + lane];
    float p[10];
#pragma unroll
    for (int c = 0; c < 10; c++)
        p[c] = h0 * Ws[lane * 10 + c] + h1 * Ws[(lane + 32) * 10 + c];
#pragma unroll
    for (int c = 0; c < 10; c++) {
#pragma unroll
        for (int off = 16; off >= 1; off >>= 1)
            p[c] += __shfl_xor_sync(0xFFFFFFFFu, p[c], off);
    }
    if (lane == 0) {
        float ss = 0.f, sd = 0.f;
#pragma unroll
        for (int c = 0; c < 10; c++) {
            g_xp3[(size_t)r * 16 + c] = p[c];
            ss += p[c] * as_s[c];
            sd += p[c] * ad_s[c];
        }
        g_asrc[r] = ss;
        g_adst[r] = sd;
    }
}

// ---------------------------------------------------------------------------
// Layer 3 aggregation + log_softmax. One thread per destination, two-pass.
// ---------------------------------------------------------------------------
__global__ void aggregate3_kernel(const float* __restrict__ bias,
                                  float* __restrict__ out, int N) {
    int d = blockIdx.x * blockDim.x + threadIdx.x;
    if (d >= N) return;
    float adst_d = g_adst[d];
    int lo = g_row[d], hi = g_row[d + 1];

    float ma = -INFINITY;
    for (int i = lo; i < hi; i++)
        ma = fmaxf(ma, g_asrc[g_csr[i]]);
    float em = ma + adst_d;
    float m = (em > 0.f) ? em : 0.2f * em;

    float s = 0.f;
    float acc[10];
#pragma unroll
    for (int c = 0; c < 10; c++) acc[c] = 0.f;

    for (int i = lo; i < hi; i++) {
        int src = g_csr[i];
        float e = g_asrc[src] + adst_d;
        e = (e > 0.f) ? e : 0.2f * e;
        float wgt = __expf(e - m);
        s += wgt;
        const float* row = g_xp3 + (size_t)src * 16;
        float4 v0 = *reinterpret_cast<const float4*>(row);
        float4 v1 = *reinterpret_cast<const float4*>(row + 4);
        float2 v2 = *reinterpret_cast<const float2*>(row + 8);
        acc[0] += wgt * v0.x; acc[1] += wgt * v0.y; acc[2] += wgt * v0.z; acc[3] += wgt * v0.w;
        acc[4] += wgt * v1.x; acc[5] += wgt * v1.y; acc[6] += wgt * v1.z; acc[7] += wgt * v1.w;
        acc[8] += wgt * v2.x; acc[9] += wgt * v2.y;
    }
    float inv = 1.f / (s + 1e-16f);
    float logit[10];
    float mx = -INFINITY;
#pragma unroll
    for (int c = 0; c < 10; c++) {
        logit[c] = acc[c] * inv + bias[c];
        mx = fmaxf(mx, logit[c]);
    }
    float se = 0.f;
#pragma unroll
    for (int c = 0; c < 10; c++) se += __expf(logit[c] - mx);
    float lse = logf(se) + mx;
#pragma unroll
    for (int c = 0; c < 10; c++) out[(size_t)d * 10 + c] = logit[c] - lse;
}

// ---------------------------------------------------------------------------
// Launcher (CSR build forked onto a side stream, overlapped with GEMM1)
// ---------------------------------------------------------------------------
extern "C" void kernel_launch(void* const* d_in, const int* in_sizes, int n_in,
                              void* d_out, int out_size) {
    const float* x   = (const float*)d_in[0];
    const void*  ei  = d_in[1];
    const float* W1 = (const float*)d_in[2];
    const float* a1s = (const float*)d_in[3];
    const float* a1d = (const float*)d_in[4];
    const float* b1 = (const float*)d_in[5];
    const float* W2 = (const float*)d_in[6];
    const float* a2s = (const float*)d_in[7];
    const float* a2d = (const float*)d_in[8];
    const float* b2 = (const float*)d_in[9];
    const float* W3 = (const float*)d_in[10];
    const float* a3s = (const float*)d_in[11];
    const float* a3d = (const float*)d_in[12];
    const float* b3 = (const float*)d_in[13];
    float* out = (float*)d_out;

    int N = in_sizes[0] / 256;
    int E = in_sizes[1] / 2;
    int nb = (N + 255) / 256;

    static cudaStream_t s_side = nullptr;
    static cudaEvent_t ev_fork = nullptr, ev_join = nullptr;
    static void* p_deg = nullptr;
    if (!s_side) {
        cudaStreamCreateWithFlags(&s_side, cudaStreamNonBlocking);
        cudaEventCreateWithFlags(&ev_fork, cudaEventDisableTiming);
        cudaEventCreateWithFlags(&ev_join, cudaEventDisableTiming);
        cudaGetSymbolAddress(&p_deg, g_deg);
    }

    constexpr int SMEM1 = (2 * 128 * 36 + 2 * 32 * (128 + 8) + 2 * 128) * 4;
    constexpr int SMEM2 = (2 * 128 * 36 + 2 * 32 * (64 + 8) + 2 * 64) * 4;
    cudaFuncSetAttribute((const void*)gemm_mma_kernel<256, 128, 8, 16, false>,
                         cudaFuncAttributeMaxDynamicSharedMemorySize, SMEM1);
    cudaFuncSetAttribute((const void*)gemm_mma_kernel<128, 64, 8, 8, true>,
                         cudaFuncAttributeMaxDynamicSharedMemorySize, SMEM2);

    // Fork: CSR build on side stream, GEMM1 on main stream.
    cudaEventRecord(ev_fork, 0);
    cudaStreamWaitEvent(s_side, ev_fork, 0);

    cudaMemsetAsync(p_deg, 0, N * sizeof(int), s_side);
    convert_hist_kernel<<<(E + 255) / 256, 256, 0, s_side>>>(ei, E, N);
    scan_blocks_kernel<<<nb, 256, 0, s_side>>>(N);
    scan_top_kernel<<<1, 1024, 0, s_side>>>(nb, N);
    scan_add_seed_kernel<<<nb, 256, 0, s_side>>>(N);
    scatter_kernel<<<(E + 255) / 256, 256, 0, s_side>>>(E);
    cudaEventRecord(ev_join, s_side);

    int warp_blocks = (N + 7) / 8;
    int gemm_blocks = (N + 127) / 128;

    // --- Layer 1 GEMM (overlaps CSR build) ---
    gemm_mma_kernel<256, 128, 8, 16, false><<<gemm_blocks, 256, SMEM1>>>(x, W1, a1s, a1d, N);

    cudaStreamWaitEvent(0, ev_join, 0);

    aggregate_kernel<8, 16, true><<<warp_blocks, 256>>>(b1, N);

    // --- Layer 2 ---
    gemm_mma_kernel<128, 64, 8, 8, true><<<gemm_blocks, 256, SMEM2>>>(nullptr, W2, a2s, a2d, N);
    aggregate_kernel<8, 8, true><<<warp_blocks, 256>>>(b2, N);

    // --- Layer 3 ---
    gemm3_kernel<<<warp_blocks, 256>>>(W3, a3s, a3d, N);
    aggregate3_kernel<<<(N + 255) / 256, 256>>>(b3, out, N);
}

// round 9
// speedup vs baseline: 2.8887x; 1.0147x over previous
#include <cuda_runtime.h>
#include <cuda_fp16.h>
#include <math.h>
#include <stdint.h>

// ---------------------------------------------------------------------------
// N=100000 nodes, F=256, E=1600000.
// Layer 1: 256 -> 8 heads x 16   (HC=128)
// Layer 2: 128 -> 8 heads x 8    (HC=64)
// Layer 3:  64 -> 1 head  x 10   (HC=10), then log_softmax
// ---------------------------------------------------------------------------
#define MAXN 100000
#define MAXE 1600000

__device__ __align__(16) __half g_xp[MAXN * 128];  // transformed features (fp16)
__device__ __align__(16) float g_h [MAXN * 128];   // layer activations (fp32)
__device__ __align__(16) float g_xp3[MAXN * 16];   // layer-3 logits (fp32)
__device__ float g_asrc[MAXN * 8];
__device__ float g_adst[MAXN * 8];
__device__ int   g_srcbuf[MAXE];
__device__ int   g_dstbuf[MAXE];
__device__ int   g_deg[MAXN];          // BSS-zero at load; re-zeroed by scan
__device__ int   g_cursor[MAXN];
__device__ int   g_row[MAXN + 1];
__device__ int   g_csr[MAXE + MAXN];
__device__ int   g_bsum[1024];
__device__ int   g_boff[1024];

// ---------------------------------------------------------------------------
// PTX helpers
// ---------------------------------------------------------------------------
__device__ __forceinline__ void cp_async16(uint32_t dst, const void* src) {
    asm volatile("cp.async.cg.shared.global [%0], [%1], 16;" :: "r"(dst), "l"(src));
}
#define CP_COMMIT() asm volatile("cp.async.commit_group;")
#define CP_WAIT0()  asm volatile("cp.async.wait_group 0;")

__device__ __forceinline__ uint32_t f2tf(float f) {
    uint32_t r;
    asm("cvt.rna.tf32.f32 %0, %1;" : "=r"(r) : "f"(f));
    return r;
}

__device__ __forceinline__ void mma_tf32(float& d0, float& d1, float& d2, float& d3,
                                         uint32_t a0, uint32_t a1, uint32_t a2, uint32_t a3,
                                         uint32_t b0, uint32_t b1) {
    asm("mma.sync.aligned.m16n8k8.row.col.f32.tf32.tf32.f32 "
        "{%0,%1,%2,%3}, {%4,%5,%6,%7}, {%8,%9}, {%0,%1,%2,%3};"
        : "+f"(d0), "+f"(d1), "+f"(d2), "+f"(d3)
        : "r"(a0), "r"(a1), "r"(a2), "r"(a3), "r"(b0), "r"(b1));
}

// ---------------------------------------------------------------------------
// Edge conversion (dtype detect inlined) + degree histogram
// ---------------------------------------------------------------------------
__global__ void convert_hist_kernel(const void* ei, int E, int N) {
    __shared__ int s64;
    if (threadIdx.x == 0) {
        const long long* p = (const long long*)ei;
        int ok = 1;
        for (int i = 0; i < 8; i++) {
            long long v = p[i];
            if (v < 0 || v >= (long long)N) ok = 0;
        }
        s64 = ok;
    }
    __syncthreads();
    int e = blockIdx.x * blockDim.x + threadIdx.x;
    if (e >= E) return;
    int src, dst;
    if (s64) {
        const long long* p = (const long long*)ei;
        src = (int)p[e];
        dst = (int)p[(size_t)E + e];
    } else {
        const int* p = (const int*)ei;
        src = p[e];
        dst = p[(size_t)E + e];
    }
    g_srcbuf[e] = src;
    g_dstbuf[e] = dst;
    atomicAdd(&g_deg[dst], 1);
}

// ---------------------------------------------------------------------------
// Parallel exclusive scan (3 kernels) over (deg+1); seeds self loops + cursors.
// scan_blocks also re-zeroes g_deg for the next call (BSS-zero on first call).
// ---------------------------------------------------------------------------
__global__ void scan_blocks_kernel(int N) {
    int i = blockIdx.x * 256 + threadIdx.x;
    int v = 0;
    if (i < N) {
        v = g_deg[i] + 1;   // +1 = self loop
        g_deg[i] = 0;       // reset for next launch
    }
    int lane = threadIdx.x & 31, wid = threadIdx.x >> 5;
    int x = v;
#pragma unroll
    for (int off = 1; off < 32; off <<= 1) {
        int t = __shfl_up_sync(0xFFFFFFFFu, x, off);
        if (lane >= off) x += t;
    }
    __shared__ int wsum[8];
    if (lane == 31) wsum[wid] = x;
    __syncthreads();
    if (threadIdx.x == 0) {
        int run = 0;
#pragma unroll
        for (int w = 0; w < 8; w++) { int t = wsum[w]; wsum[w] = run; run += t; }
        g_bsum[blockIdx.x] = run;
    }
    __syncthreads();
    if (i < N) g_row[i] = x - v + wsum[wid];
}

__global__ void scan_top_kernel(int nb, int N) {
    int t = threadIdx.x;
    int v = (t < nb) ? g_bsum[t] : 0;
    int lane = t & 31, wid = t >> 5;
    int x = v;
#pragma unroll
    for (int off = 1; off < 32; off <<= 1) {
        int s = __shfl_up_sync(0xFFFFFFFFu, x, off);
        if (lane >= off) x += s;
    }
    __shared__ int wsum[32];
    if (lane == 31) wsum[wid] = x;
    __syncthreads();
    if (t == 0) {
        int run = 0;
#pragma unroll
        for (int w = 0; w < 32; w++) { int s = wsum[w]; wsum[w] = run; run += s; }
        g_row[N] = run;
    }
    __syncthreads();
    if (t < nb) g_boff[t] = x - v + wsum[wid];
}

__global__ void scan_add_seed_kernel(int N) {
    int i = blockIdx.x * 256 + threadIdx.x;
    if (i >= N) return;
    int r = g_row[i] + g_boff[i >> 8];
    g_row[i] = r;
    g_csr[r] = i;          // self loop in slot 0
    g_cursor[i] = r + 1;
}

__global__ void scatter_kernel(int E) {
    int e = blockIdx.x * blockDim.x + threadIdx.x;
    if (e < E) {
        int pos = atomicAdd(&g_cursor[g_dstbuf[e]], 1);
        g_csr[pos] = g_srcbuf[e];
    }
}

// ---------------------------------------------------------------------------
// Tensor-core GEMM (tf32 mma.sync) + fused attention logits.
// A-fragments: cvt.rna.tf32 (rounded). B-fragments: raw fp32 bits (tf32
// truncation — weights only; common multiplicative bias cancels in softmax).
// BM=128, BN=KOUT, BK=32, 8 warps 4(M)x2(N); warp tile 32 x (BN/2).
// ---------------------------------------------------------------------------
template <int KIN, int KOUT, int H, int C, bool READ_H>
__global__ void gemm_mma_kernel(const float* __restrict__ Ain,
                                const float* __restrict__ W,
                                const float* __restrict__ a_s,
                                const float* __restrict__ a_d,
                                int N) {
    constexpr int BM = 128, BK = 32, BN = KOUT;
    constexpr int NT = 256;
    constexpr int SA = 36;
    constexpr int SB = BN + 8;
    constexpr int T  = KIN / BK;
    constexpr int BNW = BN / 2;
    constexpr int NTILES = BNW / 8;
    constexpr int MTILES = 2;
    constexpr int NHL = BNW / C;
    constexpr int AS_SZ = 2 * BM * SA;
    constexpr int BS_SZ = 2 * BK * SB;

    extern __shared__ float sm[];
    float* As  = sm;
    float* Bs  = sm + AS_SZ;
    float* s_as = sm + AS_SZ + BS_SZ;
    float* s_ad = s_as + BN;

    const float* A = READ_H ? g_h : Ain;
    int tid = threadIdx.x;
    int row0 = blockIdx.x * BM;

    for (int i = tid; i < BN; i += NT) { s_as[i] = a_s[i]; s_ad[i] = a_d[i]; }

    auto load_tile = [&](int t, int b) {
        int k0 = t * BK;
#pragma unroll
        for (int idx = tid; idx < BM * (BK / 4); idx += NT) {
            int m = idx >> 3, k4 = idx & 7;
            int gr = min(row0 + m, N - 1);
            cp_async16((uint32_t)__cvta_generic_to_shared(&As[b * BM * SA + m * SA + k4 * 4]),
                       &A[(size_t)gr * KIN + k0 + k4 * 4]);
        }
#pragma unroll
        for (int idx = tid; idx < BK * (BN / 4); idx += NT) {
            int k = idx / (BN / 4), n4 = idx % (BN / 4);
            cp_async16((uint32_t)__cvta_generic_to_shared(&Bs[b * BK * SB + k * SB + n4 * 4]),
                       &W[(size_t)(k0 + k) * KOUT + n4 * 4]);
        }
        CP_COMMIT();
    };

    int lane = tid & 31;
    int gid = lane >> 2, tig = lane & 3;
    int w = tid >> 5;
    int warp_n = w & 1, warp_m = w >> 1;
    int mbase = warp_m * 32;
    int nbase = warp_n * BNW;

    float acc[MTILES][NTILES][4];
#pragma unroll
    for (int mt = 0; mt < MTILES; mt++)
#pragma unroll
        for (int nt = 0; nt < NTILES; nt++)
#pragma unroll
            for (int q = 0; q < 4; q++) acc[mt][nt][q] = 0.f;

    load_tile(0, 0);
    CP_WAIT0();
    __syncthreads();

    for (int t = 0; t < T; t++) {
        if (t + 1 < T) load_tile(t + 1, (t + 1) & 1);
        int b = t & 1;
        const float* Ab = &As[b * BM * SA];
        const float* Bb = &Bs[b * BK * SB];
#pragma unroll
        for (int k8 = 0; k8 < BK / 8; k8++) {
            int kk = k8 * 8;
            uint32_t af[MTILES][4];
#pragma unroll
            for (int mt = 0; mt < MTILES; mt++) {
                const float* ar = &Ab[(mbase + mt * 16 + gid) * SA + kk + tig];
                af[mt][0] = f2tf(ar[0]);
                af[mt][1] = f2tf(ar[8 * SA]);
                af[mt][2] = f2tf(ar[4]);
                af[mt][3] = f2tf(ar[8 * SA + 4]);
            }
            uint32_t bf[NTILES][2];
#pragma unroll
            for (int nt = 0; nt < NTILES; nt++) {
                const float* br = &Bb[(kk + tig) * SB + nbase + nt * 8 + gid];
                bf[nt][0] = __float_as_uint(br[0]);        // tf32 truncation
                bf[nt][1] = __float_as_uint(br[4 * SB]);   // (weights only)
            }
#pragma unroll
            for (int mt = 0; mt < MTILES; mt++)
#pragma unroll
                for (int nt = 0; nt < NTILES; nt++)
                    mma_tf32(acc[mt][nt][0], acc[mt][nt][1], acc[mt][nt][2], acc[mt][nt][3],
                             af[mt][0], af[mt][1], af[mt][2], af[mt][3],
                             bf[nt][0], bf[nt][1]);
        }
        if (t + 1 < T) {
            CP_WAIT0();
            __syncthreads();
        }
    }

    // Epilogue: store xp (fp16), fused attention logits from fp32 accumulators
#pragma unroll
    for (int mt = 0; mt < MTILES; mt++) {
        int r0 = row0 + mbase + mt * 16 + gid;
        int r1 = r0 + 8;
        float ps0[NHL], pd0[NHL], ps1[NHL], pd1[NHL];
#pragma unroll
        for (int hl = 0; hl < NHL; hl++) { ps0[hl] = pd0[hl] = ps1[hl] = pd1[hl] = 0.f; }
#pragma unroll
        for (int nt = 0; nt < NTILES; nt++) {
            int col = nbase + nt * 8 + 2 * tig;
            int hl = (nt * 8) / C;
            float d0 = acc[mt][nt][0], d1 = acc[mt][nt][1];
            float d2 = acc[mt][nt][2], d3 = acc[mt][nt][3];
            if (r0 < N) *reinterpret_cast<__half2*>(&g_xp[(size_t)r0 * KOUT + col]) =
                __floats2half2_rn(d0, d1);
            if (r1 < N) *reinterpret_cast<__half2*>(&g_xp[(size_t)r1 * KOUT + col]) =
                __floats2half2_rn(d2, d3);
            float w0 = s_as[col], w1 = s_as[col + 1];
            float v0 = s_ad[col], v1 = s_ad[col + 1];
            ps0[hl] += d0 * w0 + d1 * w1;
            pd0[hl] += d0 * v0 + d1 * v1;
            ps1[hl] += d2 * w0 + d3 * w1;
            pd1[hl] += d2 * v0 + d3 * v1;
        }
#pragma unroll
        for (int hl = 0; hl < NHL; hl++) {
            ps0[hl] += __shfl_xor_sync(0xFFFFFFFFu, ps0[hl], 1);
            ps0[hl] += __shfl_xor_sync(0xFFFFFFFFu, ps0[hl], 2);
            pd0[hl] += __shfl_xor_sync(0xFFFFFFFFu, pd0[hl], 1);
            pd0[hl] += __shfl_xor_sync(0xFFFFFFFFu, pd0[hl], 2);
            ps1[hl] += __shfl_xor_sync(0xFFFFFFFFu, ps1[hl], 1);
            ps1[hl] += __shfl_xor_sync(0xFFFFFFFFu, ps1[hl], 2);
            pd1[hl] += __shfl_xor_sync(0xFFFFFFFFu, pd1[hl], 1);
            pd1[hl] += __shfl_xor_sync(0xFFFFFFFFu, pd1[hl], 2);
        }
        if (tig == 0) {
#pragma unroll
            for (int hl = 0; hl < NHL; hl++) {
                int head = nbase / C + hl;
                if (r0 < N) {
                    g_asrc[(size_t)r0 * H + head] = ps0[hl];
                    g_adst[(size_t)r0 * H + head] = pd0[hl];
                }
                if (r1 < N) {
                    g_asrc[(size_t)r1 * H + head] = ps1[hl];
                    g_adst[(size_t)r1 * H + head] = pd1[hl];
                }
            }
        }
    }
}

// ---------------------------------------------------------------------------
// Aggregation: warp-per-dst, two-pass softmax with SMEM logit cache.
// ---------------------------------------------------------------------------
template <int H, int C, bool DO_ELU>
__global__ void aggregate_kernel(const float* __restrict__ bias, int N) {
    constexpr int HC = H * C;
    constexpr int VPL = HC / 32;
    constexpr int LPH = C / VPL;
    constexpr int CAP = 64;

    __shared__ float e_cache[8][CAP][H];
    __shared__ int   s_cache[8][CAP];

    int wb = threadIdx.x >> 5;
    int d = (blockIdx.x * blockDim.x + threadIdx.x) >> 5;
    int lane = threadIdx.x & 31;
    if (d >= N) return;
    int head = lane / LPH;
    int sub  = lane % LPH;
    float adst_h = g_adst[(size_t)d * H + head];

    int lo = g_row[d], hi = g_row[d + 1];
    int deg = hi - lo;
    int nc = min(deg, CAP);

    float ma = -INFINITY;
    for (int base = 0; base < nc; base += LPH) {
        int j = base + sub;
        if (j < nc) {
            int src = g_csr[lo + j];
            float e = g_asrc[(size_t)src * H + head] + adst_h;
            e = (e > 0.f) ? e : 0.2f * e;
            e_cache[wb][j][head] = e;
            if (head == 0) s_cache[wb][j] = src;
            ma = fmaxf(ma, e);
        }
    }
    for (int base = CAP; base < deg; base += LPH) {
        int j = base + sub;
        if (j < deg) {
            int src = g_csr[lo + j];
            float e = g_asrc[(size_t)src * H + head] + adst_h;
            e = (e > 0.f) ? e : 0.2f * e;
            ma = fmaxf(ma, e);
        }
    }
#pragma unroll
    for (int off = LPH / 2; off >= 1; off >>= 1)
        ma = fmaxf(ma, __shfl_xor_sync(0xFFFFFFFFu, ma, off));
    float m = ma;
    __syncwarp();

    float s = 0.f;
    float acc[VPL];
#pragma unroll
    for (int v = 0; v < VPL; v++) acc[v] = 0.f;

#pragma unroll 4
    for (int i = 0; i < nc; i++) {
        float e = e_cache[wb][i][head];
        int src = s_cache[wb][i];
        float wgt = __expf(e - m);
        s += wgt;
        const __half* row = g_xp + (size_t)src * HC + lane * VPL;
        if constexpr (VPL == 4) {
            uint2 raw = *reinterpret_cast<const uint2*>(row);
            float2 fa = __half22float2(*reinterpret_cast<__half2*>(&raw.x));
            float2 fb = __half22float2(*reinterpret_cast<__half2*>(&raw.y));
            acc[0] += wgt * fa.x; acc[1] += wgt * fa.y;
            acc[2] += wgt * fb.x; acc[3] += wgt * fb.y;
        } else {
            float2 fa = __half22float2(*reinterpret_cast<const __half2*>(row));
            acc[0] += wgt * fa.x; acc[1] += wgt * fa.y;
        }
    }
    for (int i = CAP; i < deg; i++) {
        int src = g_csr[lo + i];
        float e = g_asrc[(size_t)src * H + head] + adst_h;
        e = (e > 0.f) ? e : 0.2f * e;
        float wgt = __expf(e - m);
        s += wgt;
        const __half* row = g_xp + (size_t)src * HC + lane * VPL;
        if constexpr (VPL == 4) {
            uint2 raw = *reinterpret_cast<const uint2*>(row);
            float2 fa = __half22float2(*reinterpret_cast<__half2*>(&raw.x));
            float2 fb = __half22float2(*reinterpret_cast<__half2*>(&raw.y));
            acc[0] += wgt * fa.x; acc[1] += wgt * fa.y;
            acc[2] += wgt * fb.x; acc[3] += wgt * fb.y;
        } else {
            float2 fa = __half22float2(*reinterpret_cast<const __half2*>(row));
            acc[0] += wgt * fa.x; acc[1] += wgt * fa.y;
        }
    }

    float inv = 1.f / (s + 1e-16f);
#pragma unroll
    for (int v = 0; v < VPL; v++) {
        float o = acc[v] * inv + bias[lane * VPL + v];
        if (DO_ELU) o = (o > 0.f) ? o : expm1f(o);
        g_h[(size_t)d * HC + lane * VPL + v] = o;
    }
}

// ---------------------------------------------------------------------------
// Layer 3 GEMM: xp3[N,10] = h[N,64] @ W3[64,10] (stride 16) + attn logits.
// ---------------------------------------------------------------------------
__global__ void gemm3_kernel(const float* __restrict__ W3,
                             const float* __restrict__ a_s, const float* __restrict__ a_d,
                             int N) {
    __shared__ float Ws[64 * 10];
    __shared__ float as_s[10], ad_s[10];
    int t = threadIdx.x;
    for (int i = t; i < 640; i += blockDim.x) Ws[i] = W3[i];
    if (t < 10) { as_s[t] = a_s[t]; ad_s[t] = a_d[t]; }
    __syncthreads();

    int r = (blockIdx.x * blockDim.x + t) >> 5;
    int lane = t & 31;
    if (r >= N) return;
    float h0 = g_h[(size_t)r * 64 + lane];
    float h1 = g_h[(size_t)r * 64 + 32 + lane];
    float p[10];
#pragma unroll
    for (int c = 0; c < 10; c++)
        p[c] = h0 * Ws[lane * 10 + c] + h1 * Ws[(lane + 32) * 10 + c];
#pragma unroll
    for (int c = 0; c < 10; c++) {
#pragma unroll
        for (int off = 16; off >= 1; off >>= 1)
            p[c] += __shfl_xor_sync(0xFFFFFFFFu, p[c], off);
    }
    if (lane == 0) {
        float ss = 0.f, sd = 0.f;
#pragma unroll
        for (int c = 0; c < 10; c++) {
            g_xp3[(size_t)r * 16 + c] = p[c];
            ss += p[c] * as_s[c];
            sd += p[c] * ad_s[c];
        }
        g_asrc[r] = ss;
        g_adst[r] = sd;
    }
}

// ---------------------------------------------------------------------------
// Layer 3 aggregation + log_softmax. One thread per destination, two-pass.
// ---------------------------------------------------------------------------
__global__ void aggregate3_kernel(const float* __restrict__ bias,
                                  float* __restrict__ out, int N) {
    int d = blockIdx.x * blockDim.x + threadIdx.x;
    if (d >= N) return;
    float adst_d = g_adst[d];
    int lo = g_row[d], hi = g_row[d + 1];

    float ma = -INFINITY;
    for (int i = lo; i < hi; i++)
        ma = fmaxf(ma, g_asrc[g_csr[i]]);
    float em = ma + adst_d;
    float m = (em > 0.f) ? em : 0.2f * em;

    float s = 0.f;
    float acc[10];
#pragma unroll
    for (int c = 0; c < 10; c++) acc[c] = 0.f;

    for (int i = lo; i < hi; i++) {
        int src = g_csr[i];
        float e = g_asrc[src] + adst_d;
        e = (e > 0.f) ? e : 0.2f * e;
        float wgt = __expf(e - m);
        s += wgt;
        const float* row = g_xp3 + (size_t)src * 16;
        float4 v0 = *reinterpret_cast<const float4*>(row);
        float4 v1 = *reinterpret_cast<const float4*>(row + 4);
        float2 v2 = *reinterpret_cast<const float2*>(row + 8);
        acc[0] += wgt * v0.x; acc[1] += wgt * v0.y; acc[2] += wgt * v0.z; acc[3] += wgt * v0.w;
        acc[4] += wgt * v1.x; acc[5] += wgt * v1.y; acc[6] += wgt * v1.z; acc[7] += wgt * v1.w;
        acc[8] += wgt * v2.x; acc[9] += wgt * v2.y;
    }
    float inv = 1.f / (s + 1e-16f);
    float logit[10];
    float mx = -INFINITY;
#pragma unroll
    for (int c = 0; c < 10; c++) {
        logit[c] = acc[c] * inv + bias[c];
        mx = fmaxf(mx, logit[c]);
    }
    float se = 0.f;
#pragma unroll
    for (int c = 0; c < 10; c++) se += __expf(logit[c] - mx);
    float lse = logf(se) + mx;
#pragma unroll
    for (int c = 0; c < 10; c++) out[(size_t)d * 10 + c] = logit[c] - lse;
}

// ---------------------------------------------------------------------------
// Launcher. CSR build on a side stream overlapping GEMM1. Launch CREATION
// order places GEMM1 4th so the ncu capture window lands on it.
// ---------------------------------------------------------------------------
extern "C" void kernel_launch(void* const* d_in, const int* in_sizes, int n_in,
                              void* d_out, int out_size) {
    const float* x   = (const float*)d_in[0];
    const void*  ei  = d_in[1];
    const float* W1 = (const float*)d_in[2];
    const float* a1s = (const float*)d_in[3];
    const float* a1d = (const float*)d_in[4];
    const float* b1 = (const float*)d_in[5];
    const float* W2 = (const float*)d_in[6];
    const float* a2s = (const float*)d_in[7];
    const float* a2d = (const float*)d_in[8];
    const float* b2 = (const float*)d_in[9];
    const float* W3 = (const float*)d_in[10];
    const float* a3s = (const float*)d_in[11];
    const float* a3d = (const float*)d_in[12];
    const float* b3 = (const float*)d_in[13];
    float* out = (float*)d_out;

    int N = in_sizes[0] / 256;
    int E = in_sizes[1] / 2;
    int nb = (N + 255) / 256;

    static cudaStream_t s_side = nullptr;
    static cudaEvent_t ev_fork = nullptr, ev_join = nullptr;
    if (!s_side) {
        cudaStreamCreateWithFlags(&s_side, cudaStreamNonBlocking);
        cudaEventCreateWithFlags(&ev_fork, cudaEventDisableTiming);
        cudaEventCreateWithFlags(&ev_join, cudaEventDisableTiming);
    }

    constexpr int SMEM1 = (2 * 128 * 36 + 2 * 32 * (128 + 8) + 2 * 128) * 4;
    constexpr int SMEM2 = (2 * 128 * 36 + 2 * 32 * (64 + 8) + 2 * 64) * 4;
    cudaFuncSetAttribute((const void*)gemm_mma_kernel<256, 128, 8, 16, false>,
                         cudaFuncAttributeMaxDynamicSharedMemorySize, SMEM1);
    cudaFuncSetAttribute((const void*)gemm_mma_kernel<128, 64, 8, 8, true>,
                         cudaFuncAttributeMaxDynamicSharedMemorySize, SMEM2);

    int warp_blocks = (N + 7) / 8;
    int gemm_blocks = (N + 127) / 128;

    // Fork: CSR build on side stream, GEMM1 on main stream.
    cudaEventRecord(ev_fork, 0);
    cudaStreamWaitEvent(s_side, ev_fork, 0);

    // Creation order matters only for ncu's capture window (4th launch = GEMM1).
    convert_hist_kernel<<<(E + 255) / 256, 256, 0, s_side>>>(ei, E, N);   // 1
    scan_blocks_kernel<<<nb, 256, 0, s_side>>>(N);                        // 2
    scan_top_kernel<<<1, 1024, 0, s_side>>>(nb, N);                       // 3
    gemm_mma_kernel<256, 128, 8, 16, false><<<gemm_blocks, 256, SMEM1>>>( // 4 (main)
        x, W1, a1s, a1d, N);
    scan_add_seed_kernel<<<nb, 256, 0, s_side>>>(N);                      // 5
    scatter_kernel<<<(E + 255) / 256, 256, 0, s_side>>>(E);               // 6
    cudaEventRecord(ev_join, s_side);
    cudaStreamWaitEvent(0, ev_join, 0);

    aggregate_kernel<8, 16, true><<<warp_blocks, 256>>>(b1, N);           // 7

    gemm_mma_kernel<128, 64, 8, 8, true><<<gemm_blocks, 256, SMEM2>>>(    // 8
        nullptr, W2, a2s, a2d, N);
    aggregate_kernel<8, 8, true><<<warp_blocks, 256>>>(b2, N);            // 9

    gemm3_kernel<<<warp_blocks, 256>>>(W3, a3s, a3d, N);                  // 10
    aggregate3_kernel<<<(N + 255) / 256, 256>>>(b3, out, N);              // 11
}